// round 5
// baseline (speedup 1.0000x reference)
#include <cuda_runtime.h>
#include <cuda_fp16.h>
#include <cstdint>

#define B_SZ 4
#define L_SZ 2048
#define DM   1024
#define H_N  16
#define DK   64
#define BH   64
#define ROWS 8192
#define EPS_Z 1e-8f
#define NSPLIT 16

// ---------------- scratch ----------------------------------------------------
__device__ __half g_Wh[4][DM * DM];        // fp16 weights (wq,wk,wv,wo)
__device__ __half g_Ah[3][ROWS * DM];      // fp16 inputs (q,k,v)
__device__ __half g_Qp[ROWS * DM];
__device__ __half g_Kp[ROWS * DM];
__device__ __half g_Vp[ROWS * DM];
__device__ __half g_Mid[ROWS * DM];
__device__ float  g_kv_part[NSPLIT * BH * DK * DK];
__device__ float  g_ks_part[NSPLIT * BH * DK];
__device__ float  g_KV[BH * DK * DK];
__device__ float  g_Ksum[BH * DK];

// ---------------- helpers ----------------------------------------------------
__device__ __forceinline__ float feature_map(float x) {
    return x > 0.0f ? x + 1.0f : expf(x);
}
__device__ __forceinline__ uint32_t su32(const void* p) {
    uint32_t a;
    asm("{ .reg .u64 t; cvta.to.shared.u64 t, %1; cvt.u32.u64 %0, t; }" : "=r"(a) : "l"(p));
    return a;
}
#define CP16(s, g) asm volatile("cp.async.cg.shared.global [%0], [%1], 16;" :: "r"(s), "l"(g))
#define CP_COMMIT() asm volatile("cp.async.commit_group;")
#define SWZ(o) ((o) ^ (((o) >> 3) & 0x70))

__device__ __forceinline__ void ldm_x4(uint32_t* r, uint32_t addr) {
    asm volatile("ldmatrix.sync.aligned.m8n8.x4.shared.b16 {%0,%1,%2,%3}, [%4];"
                 : "=r"(r[0]), "=r"(r[1]), "=r"(r[2]), "=r"(r[3]) : "r"(addr));
}
// fp16-accumulator mma: d/c are 2 regs (4 packed halves)
__device__ __forceinline__ void mma_f16h(uint32_t& h0, uint32_t& h1,
                                         const uint32_t* a, uint32_t b0, uint32_t b1) {
    asm volatile(
        "mma.sync.aligned.m16n8k16.row.col.f16.f16.f16.f16 "
        "{%0,%1},{%2,%3,%4,%5},{%6,%7},{%0,%1};\n"
        : "+r"(h0), "+r"(h1)
        : "r"(a[0]), "r"(a[1]), "r"(a[2]), "r"(a[3]), "r"(b0), "r"(b1));
}

// ---------------- fp16 GEMM core: C = act( A[M,K] @ W[N,K]^T ) ---------------
// BM=128 BN=128 BK=64(halfs,128B rows), 256 threads (8 warps 2x4), warp 64x32.
// fp16 accumulation over K=32 chunks, promoted to fp32.
#define GBM 128
#define GBN 128
#define ABYTES (GBM * 128)        // 16384
#define BBYTES (GBN * 128)        // 16384
#define STAGEB (ABYTES + BBYTES)  // 32768
#define GSMEM  (2 * STAGEB)       // 65536

template <int OUTK>
__device__ __forceinline__
void gemm_core(const __half* __restrict__ A, const __half* __restrict__ W,
               void* __restrict__ Cv, int act, int bm0, int bn0, char* sm)
{
    const int tid = threadIdx.x;
    const int wid = tid >> 5;
    const int lane = tid & 31;
    const int wm = wid >> 2;      // 0..1
    const int wn = wid & 3;       // 0..3
    const int gid = lane >> 2;    // 0..7
    const int tig = lane & 3;     // 0..3

    const __half* Ag = A + (size_t)bm0 * DM;
    const __half* Wg = W + (size_t)bn0 * DM;
    const uint32_t sbase = su32(sm);

    float acc[4][4][4];
#pragma unroll
    for (int mi = 0; mi < 4; mi++)
#pragma unroll
        for (int ni = 0; ni < 4; ni++)
#pragma unroll
            for (int c = 0; c < 4; c++) acc[mi][ni][c] = 0.0f;

    auto load_tile = [&](int stg, int k0) {
        const uint32_t ab = sbase + stg * STAGEB;
        const uint32_t bb = ab + ABYTES;
#pragma unroll
        for (int j = 0; j < 4; j++) {          // A: 1024 x 16B chunks
            int i = tid + j * 256;
            int r = i >> 3, q = i & 7;
            CP16(ab + SWZ(r * 128 + q * 16), Ag + (size_t)r * DM + k0 + q * 8);
        }
#pragma unroll
        for (int j = 0; j < 4; j++) {          // B: 1024 x 16B chunks
            int i = tid + j * 256;
            int r = i >> 3, q = i & 7;
            CP16(bb + SWZ(r * 128 + q * 16), Wg + (size_t)r * DM + k0 + q * 8);
        }
        CP_COMMIT();
    };

    const int KT = DM / 64;    // 16
    load_tile(0, 0);

    const int lrow = lane & 15;
    const int lhi  = (lane >> 4) << 4;

    for (int t = 0; t < KT; t++) {
        const int cur = t & 1;
        if (t + 1 < KT) {
            load_tile(cur ^ 1, (t + 1) * 64);
            asm volatile("cp.async.wait_group 1;");
        } else {
            asm volatile("cp.async.wait_group 0;");
        }
        __syncthreads();

        const uint32_t ab = sbase + cur * STAGEB;
        const uint32_t bb = ab + ABYTES;

#pragma unroll
        for (int c = 0; c < 2; c++) {          // K=32 chunks
            uint32_t af[2][4][4];
            uint32_t bf[2][2][4];
#pragma unroll
            for (int s = 0; s < 2; s++) {
                const int kboff = (2 * c + s) * 32 + lhi;
#pragma unroll
                for (int mi = 0; mi < 4; mi++)
                    ldm_x4(af[s][mi], ab + SWZ((wm * 64 + mi * 16 + lrow) * 128 + kboff));
#pragma unroll
                for (int p = 0; p < 2; p++)
                    ldm_x4(bf[s][p], bb + SWZ((wn * 32 + p * 16 + lrow) * 128 + kboff));
            }
#pragma unroll
            for (int mi = 0; mi < 4; mi++)
#pragma unroll
                for (int ni = 0; ni < 4; ni++) {
                    const int p = ni >> 1, sub = ni & 1;
                    uint32_t h0 = 0, h1 = 0;
                    mma_f16h(h0, h1, af[0][mi], bf[0][p][sub], bf[0][p][sub + 2]);
                    mma_f16h(h0, h1, af[1][mi], bf[1][p][sub], bf[1][p][sub + 2]);
                    float2 lo = __half22float2(*(__half2*)&h0);
                    float2 hi = __half22float2(*(__half2*)&h1);
                    acc[mi][ni][0] += lo.x; acc[mi][ni][1] += lo.y;
                    acc[mi][ni][2] += hi.x; acc[mi][ni][3] += hi.y;
                }
        }
        __syncthreads();
    }

    // epilogue
#pragma unroll
    for (int mi = 0; mi < 4; mi++) {
        int r0 = bm0 + wm * 64 + mi * 16 + gid;
#pragma unroll
        for (int ni = 0; ni < 4; ni++) {
            int c0 = bn0 + wn * 32 + ni * 8 + tig * 2;
            float v0 = acc[mi][ni][0];
            float v1 = acc[mi][ni][1];
            float v2 = acc[mi][ni][2];
            float v3 = acc[mi][ni][3];
            if (act) {
                v0 = feature_map(v0); v1 = feature_map(v1);
                v2 = feature_map(v2); v3 = feature_map(v3);
            }
            if (OUTK) {
                __half* C = (__half*)Cv;
                *(__half2*)&C[(size_t)r0 * DM + c0]       = __floats2half2_rn(v0, v1);
                *(__half2*)&C[(size_t)(r0 + 8) * DM + c0] = __floats2half2_rn(v2, v3);
            } else {
                float* C = (float*)Cv;
                *(float2*)&C[(size_t)r0 * DM + c0]       = make_float2(v0, v1);
                *(float2*)&C[(size_t)(r0 + 8) * DM + c0] = make_float2(v2, v3);
            }
        }
    }
}

// merged Q/K/V projection: grid.z selects input/weight/output
__global__ __launch_bounds__(256, 1)
void gemm_qkv(const __half* __restrict__ Ah, const __half* __restrict__ Wh,
              __half* __restrict__ Qp, __half* __restrict__ Kp, __half* __restrict__ Vp)
{
    extern __shared__ __align__(16) char sm[];
    const int z = blockIdx.z;
    const __half* A = Ah + (size_t)z * ROWS * DM;
    const __half* W = Wh + (size_t)z * DM * DM;
    __half* C = (z == 0) ? Qp : (z == 1) ? Kp : Vp;
    gemm_core<1>(A, W, (void*)C, z < 2 ? 1 : 0,
                 blockIdx.y * GBM, blockIdx.x * GBN, sm);
}

// final projection: fp32 out
__global__ __launch_bounds__(256, 1)
void gemm_out(const __half* __restrict__ Mid, const __half* __restrict__ Wo,
              float* __restrict__ out)
{
    extern __shared__ __align__(16) char sm[];
    gemm_core<0>(Mid, Wo, (void*)out, 0, blockIdx.y * GBM, blockIdx.x * GBN, sm);
}

// ---------------- fp32 -> fp16 converts --------------------------------------
__global__ __launch_bounds__(256)
void wcvt_kernel(const float* __restrict__ w0, const float* __restrict__ w1,
                 const float* __restrict__ w2, const float* __restrict__ w3)
{
    const float* src[4] = { w0, w1, w2, w3 };
    const float* in = src[blockIdx.y];
    __half* out = g_Wh[blockIdx.y];
    int i = blockIdx.x * 256 + threadIdx.x;
    float4 v = ((const float4*)in)[i];
    ((__half2*)out)[2 * i]     = __floats2half2_rn(v.x, v.y);
    ((__half2*)out)[2 * i + 1] = __floats2half2_rn(v.z, v.w);
}

__global__ __launch_bounds__(256)
void acvt_kernel(const float* __restrict__ in, __half* __restrict__ out)
{
    int i = blockIdx.x * 256 + threadIdx.x;
    float4 v = ((const float4*)in)[i];
    ((__half2*)out)[2 * i]     = __floats2half2_rn(v.x, v.y);
    ((__half2*)out)[2 * i + 1] = __floats2half2_rn(v.z, v.w);
}

// ---------------- per-head KV = K^T V (split over L), fp16 in ---------------
__global__ __launch_bounds__(256)
void kv_partial_kernel(const __half* __restrict__ Kp, const __half* __restrict__ Vp)
{
    const int s  = blockIdx.x;
    const int bh = blockIdx.y;
    const int b  = bh >> 4;
    const int h  = bh & 15;
    __shared__ float Ks[32 * 64];
    __shared__ float Vs[32 * 64];

    const int tid = threadIdx.x;
    const int dt = tid >> 2;
    const int mq = tid & 3;

    const size_t rb = ((size_t)(b * L_SZ + s * (L_SZ / NSPLIT))) * DM + h * DK;
    const __half* Kg = Kp + rb;
    const __half* Vg = Vp + rb;

    float4 a0 = {0,0,0,0}, a1 = {0,0,0,0}, a2 = {0,0,0,0}, a3 = {0,0,0,0};
    float sk = 0.0f;

    const int n = tid >> 3;
    const int qc = (tid & 7) * 8;

    for (int ch = 0; ch < (L_SZ / NSPLIT) / 32; ch++) {
        {
            union { uint4 u; __half2 h[4]; } UK, UV;
            UK.u = *(const uint4*)&Kg[(size_t)(ch * 32 + n) * DM + qc];
            UV.u = *(const uint4*)&Vg[(size_t)(ch * 32 + n) * DM + qc];
#pragma unroll
            for (int j = 0; j < 4; j++) {
                float2 fk = __half22float2(UK.h[j]);
                float2 fv = __half22float2(UV.h[j]);
                Ks[n * 64 + qc + 2 * j]     = fk.x;
                Ks[n * 64 + qc + 2 * j + 1] = fk.y;
                Vs[n * 64 + qc + 2 * j]     = fv.x;
                Vs[n * 64 + qc + 2 * j + 1] = fv.y;
            }
        }
        __syncthreads();
#pragma unroll 4
        for (int nn = 0; nn < 32; nn++) {
            float kd = Ks[nn * 64 + dt];
            sk += kd;
            const float4* vr = (const float4*)&Vs[nn * 64 + mq * 16];
            float4 v0 = vr[0], v1 = vr[1], v2 = vr[2], v3 = vr[3];
            a0.x += kd * v0.x; a0.y += kd * v0.y; a0.z += kd * v0.z; a0.w += kd * v0.w;
            a1.x += kd * v1.x; a1.y += kd * v1.y; a1.z += kd * v1.z; a1.w += kd * v1.w;
            a2.x += kd * v2.x; a2.y += kd * v2.y; a2.z += kd * v2.z; a2.w += kd * v2.w;
            a3.x += kd * v3.x; a3.y += kd * v3.y; a3.z += kd * v3.z; a3.w += kd * v3.w;
        }
        __syncthreads();
    }

    float4* o = (float4*)(g_kv_part + ((size_t)(s * BH + bh)) * (DK * DK) + dt * DK + mq * 16);
    o[0] = a0; o[1] = a1; o[2] = a2; o[3] = a3;
    if (mq == 0) g_ks_part[(s * BH + bh) * DK + dt] = sk;
}

__global__ __launch_bounds__(256)
void kv_combine_kernel()
{
    const int bh = blockIdx.x;
    const int t = threadIdx.x;
#pragma unroll
    for (int j = 0; j < 16; j++) {
        int e = t + j * 256;
        float sum = 0.0f;
#pragma unroll
        for (int s = 0; s < NSPLIT; s++)
            sum += g_kv_part[((size_t)(s * BH + bh)) * (DK * DK) + e];
        g_KV[(size_t)bh * (DK * DK) + e] = sum;
    }
    if (t < DK) {
        float sum = 0.0f;
#pragma unroll
        for (int s = 0; s < NSPLIT; s++)
            sum += g_ks_part[(s * BH + bh) * DK + t];
        g_Ksum[bh * DK + t] = sum;
    }
}

// ---------------- Mid(fp16) = Z * (Q @ KV) ----------------------------------
__global__ __launch_bounds__(256)
void attn_apply_kernel(const __half* __restrict__ Qp, __half* __restrict__ Mid)
{
    const int lc = blockIdx.x;
    const int bh = blockIdx.y;
    const int b = bh >> 4;
    const int h = bh & 15;

    __shared__ float KVs[DK * DK];
    __shared__ float Qs[64 * 68];
    __shared__ float Kss[DK];

    const int tid = threadIdx.x;
    const __half* Qg = Qp + ((size_t)(b * L_SZ + lc * 64)) * DM + h * DK;

#pragma unroll
    for (int j = 0; j < 4; j++) {
        int i = tid + j * 256;
        ((float4*)KVs)[i] = ((const float4*)(g_KV + (size_t)bh * (DK * DK)))[i];
    }
#pragma unroll
    for (int j = 0; j < 2; j++) {
        int i = tid + j * 256;
        int r = i >> 3, qc = (i & 7) * 8;
        union { uint4 u; __half2 h[4]; } U;
        U.u = *(const uint4*)&Qg[(size_t)r * DM + qc];
#pragma unroll
        for (int jj = 0; jj < 4; jj++) {
            float2 f = __half22float2(U.h[jj]);
            Qs[r * 68 + qc + 2 * jj]     = f.x;
            Qs[r * 68 + qc + 2 * jj + 1] = f.y;
        }
    }
    if (tid < DK) Kss[tid] = g_Ksum[bh * DK + tid];
    __syncthreads();

    const int r = tid >> 2;
    const int mq = tid & 3;

    float dot = 0.0f;
#pragma unroll
    for (int d = 0; d < DK; d++) dot += Qs[r * 68 + d] * Kss[d];
    const float z = 1.0f / (dot + EPS_Z);

    float4 a0 = {0,0,0,0}, a1 = {0,0,0,0}, a2 = {0,0,0,0}, a3 = {0,0,0,0};
#pragma unroll 8
    for (int d = 0; d < DK; d++) {
        float qd = Qs[r * 68 + d];
        const float4* kv = (const float4*)&KVs[d * 64 + mq * 16];
        float4 v0 = kv[0], v1 = kv[1], v2 = kv[2], v3 = kv[3];
        a0.x += qd * v0.x; a0.y += qd * v0.y; a0.z += qd * v0.z; a0.w += qd * v0.w;
        a1.x += qd * v1.x; a1.y += qd * v1.y; a1.z += qd * v1.z; a1.w += qd * v1.w;
        a2.x += qd * v2.x; a2.y += qd * v2.y; a2.z += qd * v2.z; a2.w += qd * v2.w;
        a3.x += qd * v3.x; a3.y += qd * v3.y; a3.z += qd * v3.z; a3.w += qd * v3.w;
    }

    __half* Og = Mid + ((size_t)(b * L_SZ + lc * 64 + r)) * DM + h * DK + mq * 16;
    union { uint4 u; __half2 h[4]; } O0, O1;
    O0.h[0] = __floats2half2_rn(a0.x * z, a0.y * z);
    O0.h[1] = __floats2half2_rn(a0.z * z, a0.w * z);
    O0.h[2] = __floats2half2_rn(a1.x * z, a1.y * z);
    O0.h[3] = __floats2half2_rn(a1.z * z, a1.w * z);
    O1.h[0] = __floats2half2_rn(a2.x * z, a2.y * z);
    O1.h[1] = __floats2half2_rn(a2.z * z, a2.w * z);
    O1.h[2] = __floats2half2_rn(a3.x * z, a3.y * z);
    O1.h[3] = __floats2half2_rn(a3.z * z, a3.w * z);
    *(uint4*)&Og[0] = O0.u;
    *(uint4*)&Og[8] = O1.u;
}

// ---------------- launch -----------------------------------------------------
extern "C" void kernel_launch(void* const* d_in, const int* in_sizes, int n_in,
                              void* d_out, int out_size)
{
    const float* q  = (const float*)d_in[0];
    const float* k  = (const float*)d_in[1];
    const float* v  = (const float*)d_in[2];
    const float* wq = (const float*)d_in[4];
    const float* wk = (const float*)d_in[5];
    const float* wv = (const float*)d_in[6];
    const float* wo = (const float*)d_in[7];
    float* out = (float*)d_out;

    __half *Wh, *Ah, *Qp, *Kp, *Vp, *Mid;
    cudaGetSymbolAddress((void**)&Wh,  g_Wh);
    cudaGetSymbolAddress((void**)&Ah,  g_Ah);
    cudaGetSymbolAddress((void**)&Qp,  g_Qp);
    cudaGetSymbolAddress((void**)&Kp,  g_Kp);
    cudaGetSymbolAddress((void**)&Vp,  g_Vp);
    cudaGetSymbolAddress((void**)&Mid, g_Mid);

    cudaFuncSetAttribute(gemm_qkv, cudaFuncAttributeMaxDynamicSharedMemorySize, GSMEM);
    cudaFuncSetAttribute(gemm_out, cudaFuncAttributeMaxDynamicSharedMemorySize, GSMEM);

    wcvt_kernel<<<dim3((DM * DM) / 4 / 256, 4), 256>>>(wq, wk, wv, wo);
    const int na = (ROWS * DM) / 4 / 256;
    acvt_kernel<<<na, 256>>>(q, Ah + 0 * (size_t)ROWS * DM);
    acvt_kernel<<<na, 256>>>(k, Ah + 1 * (size_t)ROWS * DM);
    acvt_kernel<<<na, 256>>>(v, Ah + 2 * (size_t)ROWS * DM);

    dim3 gq(DM / GBN, ROWS / GBM, 3);      // (8, 64, 3)
    gemm_qkv<<<gq, 256, GSMEM>>>(Ah, Wh, Qp, Kp, Vp);

    kv_partial_kernel<<<dim3(NSPLIT, BH), 256>>>(Kp, Vp);
    kv_combine_kernel<<<BH, 256>>>();
    attn_apply_kernel<<<dim3(L_SZ / 64, BH), 256>>>(Qp, Mid);

    dim3 gf(DM / GBN, ROWS / GBM);         // (8, 64)
    gemm_out<<<gf, 256, GSMEM>>>(Mid, Wh + 3 * (size_t)DM * DM, out);
}

// round 6
// speedup vs baseline: 1.0750x; 1.0750x over previous
#include <cuda_runtime.h>
#include <cuda_fp16.h>
#include <cstdint>

#define B_SZ 4
#define L_SZ 2048
#define DM   1024
#define H_N  16
#define DK   64
#define BH   64
#define ROWS 8192
#define EPS_Z 1e-8f
#define NSPLIT 16

// ---------------- scratch ----------------------------------------------------
__device__ __half g_Wh[4][DM * DM];        // fp16 weights (wq,wk,wv,wo)
__device__ __half g_Ah[3][ROWS * DM];      // fp16 inputs (q,k,v)
__device__ __half g_Qp[ROWS * DM];
__device__ __half g_Kp[ROWS * DM];
__device__ __half g_Vp[ROWS * DM];
__device__ __half g_Mid[ROWS * DM];
__device__ float  g_kv_part[NSPLIT * BH * DK * DK];
__device__ float  g_ks_part[NSPLIT * BH * DK];
__device__ float  g_KV[BH * DK * DK];
__device__ float  g_Ksum[BH * DK];

// ---------------- helpers ----------------------------------------------------
__device__ __forceinline__ float feature_map(float x) {
    return x > 0.0f ? x + 1.0f : expf(x);
}
__device__ __forceinline__ uint32_t su32(const void* p) {
    uint32_t a;
    asm("{ .reg .u64 t; cvta.to.shared.u64 t, %1; cvt.u32.u64 %0, t; }" : "=r"(a) : "l"(p));
    return a;
}
#define CP16(s, g) asm volatile("cp.async.cg.shared.global [%0], [%1], 16;" :: "r"(s), "l"(g))
#define CP_COMMIT() asm volatile("cp.async.commit_group;")
#define SWZ(o) ((o) ^ (((o) >> 3) & 0x70))

__device__ __forceinline__ void ldm_x4(uint32_t* r, uint32_t addr) {
    asm volatile("ldmatrix.sync.aligned.m8n8.x4.shared.b16 {%0,%1,%2,%3}, [%4];"
                 : "=r"(r[0]), "=r"(r[1]), "=r"(r[2]), "=r"(r[3]) : "r"(addr));
}
__device__ __forceinline__ void mma_f16(float* d, const uint32_t* a, const uint32_t* b) {
    asm volatile(
        "mma.sync.aligned.m16n8k16.row.col.f32.f16.f16.f32 "
        "{%0,%1,%2,%3},{%4,%5,%6,%7},{%8,%9},{%0,%1,%2,%3};\n"
        : "+f"(d[0]), "+f"(d[1]), "+f"(d[2]), "+f"(d[3])
        : "r"(a[0]), "r"(a[1]), "r"(a[2]), "r"(a[3]),
          "r"(b[0]), "r"(b[1]));
}

// ---------------- fp16 GEMM core: C = act( A[M,K] @ W[N,K]^T ) ---------------
// BM=128 BN=128 BK=64, 256 threads (8 warps 2x4), warp 64x32, f32 accum,
// 3-stage cp.async pipeline.
#define GBM 128
#define GBN 128
#define ABYTES (GBM * 128)        // 16384
#define BBYTES (GBN * 128)        // 16384
#define STAGEB (ABYTES + BBYTES)  // 32768
#define NSTAGE 3
#define GSMEM  (NSTAGE * STAGEB)  // 98304

template <int OUTK>
__device__ __forceinline__
void gemm_core(const __half* __restrict__ A, const __half* __restrict__ W,
               void* __restrict__ Cv, int act, int bm0, int bn0, char* sm)
{
    const int tid = threadIdx.x;
    const int wid = tid >> 5;
    const int lane = tid & 31;
    const int wm = wid >> 2;      // 0..1
    const int wn = wid & 3;       // 0..3
    const int gid = lane >> 2;    // 0..7
    const int tig = lane & 3;     // 0..3

    const __half* Ag = A + (size_t)bm0 * DM;
    const __half* Wg = W + (size_t)bn0 * DM;
    const uint32_t sbase = su32(sm);

    float acc[4][4][4];
#pragma unroll
    for (int mi = 0; mi < 4; mi++)
#pragma unroll
        for (int ni = 0; ni < 4; ni++)
#pragma unroll
            for (int c = 0; c < 4; c++) acc[mi][ni][c] = 0.0f;

    auto load_tile = [&](int stg, int k0) {
        const uint32_t ab = sbase + stg * STAGEB;
        const uint32_t bb = ab + ABYTES;
#pragma unroll
        for (int j = 0; j < 4; j++) {          // A: 1024 x 16B chunks
            int i = tid + j * 256;
            int r = i >> 3, q = i & 7;
            CP16(ab + SWZ(r * 128 + q * 16), Ag + (size_t)r * DM + k0 + q * 8);
        }
#pragma unroll
        for (int j = 0; j < 4; j++) {          // B: 1024 x 16B chunks
            int i = tid + j * 256;
            int r = i >> 3, q = i & 7;
            CP16(bb + SWZ(r * 128 + q * 16), Wg + (size_t)r * DM + k0 + q * 8);
        }
        CP_COMMIT();
    };

    const int KT = DM / 64;    // 16
    load_tile(0, 0);
    load_tile(1, 64);

    const int lrow = lane & 15;
    const int lhi  = (lane >> 4) << 4;

    for (int t = 0; t < KT; t++) {
        const int cur = t % NSTAGE;
        asm volatile("cp.async.wait_group 1;");
        __syncthreads();
        if (t + 2 < KT) load_tile((t + 2) % NSTAGE, (t + 2) * 64);

        const uint32_t ab = sbase + cur * STAGEB;
        const uint32_t bb = ab + ABYTES;

#pragma unroll
        for (int ks = 0; ks < 4; ks++) {       // K=16 steps
            const int kboff = ks * 32 + lhi;
            uint32_t af[4][4];
            uint32_t bf[2][4];
#pragma unroll
            for (int mi = 0; mi < 4; mi++)
                ldm_x4(af[mi], ab + SWZ((wm * 64 + mi * 16 + lrow) * 128 + kboff));
#pragma unroll
            for (int p = 0; p < 2; p++)
                ldm_x4(bf[p], bb + SWZ((wn * 32 + p * 16 + lrow) * 128 + kboff));
#pragma unroll
            for (int mi = 0; mi < 4; mi++)
#pragma unroll
                for (int ni = 0; ni < 4; ni++) {
                    const int p = ni >> 1, sub = ni & 1;
                    uint32_t b2[2] = { bf[p][sub], bf[p][sub + 2] };
                    mma_f16(acc[mi][ni], af[mi], b2);
                }
        }
        __syncthreads();
    }

    // epilogue
#pragma unroll
    for (int mi = 0; mi < 4; mi++) {
        int r0 = bm0 + wm * 64 + mi * 16 + gid;
#pragma unroll
        for (int ni = 0; ni < 4; ni++) {
            int c0 = bn0 + wn * 32 + ni * 8 + tig * 2;
            float v0 = acc[mi][ni][0];
            float v1 = acc[mi][ni][1];
            float v2 = acc[mi][ni][2];
            float v3 = acc[mi][ni][3];
            if (act) {
                v0 = feature_map(v0); v1 = feature_map(v1);
                v2 = feature_map(v2); v3 = feature_map(v3);
            }
            if (OUTK) {
                __half* C = (__half*)Cv;
                *(__half2*)&C[(size_t)r0 * DM + c0]       = __floats2half2_rn(v0, v1);
                *(__half2*)&C[(size_t)(r0 + 8) * DM + c0] = __floats2half2_rn(v2, v3);
            } else {
                float* C = (float*)Cv;
                *(float2*)&C[(size_t)r0 * DM + c0]       = make_float2(v0, v1);
                *(float2*)&C[(size_t)(r0 + 8) * DM + c0] = make_float2(v2, v3);
            }
        }
    }
}

// merged Q/K/V projection: grid.z selects input/weight/output
__global__ __launch_bounds__(256, 1)
void gemm_qkv(const __half* __restrict__ Ah, const __half* __restrict__ Wh,
              __half* __restrict__ Qp, __half* __restrict__ Kp, __half* __restrict__ Vp)
{
    extern __shared__ __align__(16) char sm[];
    const int z = blockIdx.z;
    const __half* A = Ah + (size_t)z * ROWS * DM;
    const __half* W = Wh + (size_t)z * DM * DM;
    __half* C = (z == 0) ? Qp : (z == 1) ? Kp : Vp;
    gemm_core<1>(A, W, (void*)C, z < 2 ? 1 : 0,
                 blockIdx.y * GBM, blockIdx.x * GBN, sm);
}

__global__ __launch_bounds__(256, 1)
void gemm_out(const __half* __restrict__ Mid, const __half* __restrict__ Wo,
              float* __restrict__ out)
{
    extern __shared__ __align__(16) char sm[];
    gemm_core<0>(Mid, Wo, (void*)out, 0, blockIdx.y * GBM, blockIdx.x * GBN, sm);
}

// ---------------- single fused fp32 -> fp16 convert --------------------------
// blocks [0, 4096): weights (4 x 1024);  [4096, 28672): inputs (3 x 8192)
#define WBLK 1024
#define ABLK 8192
__global__ __launch_bounds__(256)
void cvt_all(const float* __restrict__ q, const float* __restrict__ k,
             const float* __restrict__ v,
             const float* __restrict__ w0, const float* __restrict__ w1,
             const float* __restrict__ w2, const float* __restrict__ w3)
{
    const int b = blockIdx.x;
    const float* in;
    __half* out;
    int i;
    if (b < 4 * WBLK) {
        const float* wsrc[4] = { w0, w1, w2, w3 };
        int w = b >> 10;
        in = wsrc[w];
        out = g_Wh[w];
        i = (b & (WBLK - 1)) * 256 + threadIdx.x;
    } else {
        const float* asrc[3] = { q, k, v };
        int r = b - 4 * WBLK;
        int z = r / ABLK;
        in = asrc[z];
        out = g_Ah[z];
        i = (r % ABLK) * 256 + threadIdx.x;
    }
    float4 x = ((const float4*)in)[i];
    ((__half2*)out)[2 * i]     = __floats2half2_rn(x.x, x.y);
    ((__half2*)out)[2 * i + 1] = __floats2half2_rn(x.z, x.w);
}

// ---------------- per-head KV = K^T V (split over L), fp16 in ---------------
__global__ __launch_bounds__(256)
void kv_partial_kernel(const __half* __restrict__ Kp, const __half* __restrict__ Vp)
{
    const int s  = blockIdx.x;
    const int bh = blockIdx.y;
    const int b  = bh >> 4;
    const int h  = bh & 15;
    __shared__ float Ks[32 * 64];
    __shared__ float Vs[32 * 64];

    const int tid = threadIdx.x;
    const int dt = tid >> 2;
    const int mq = tid & 3;

    const size_t rb = ((size_t)(b * L_SZ + s * (L_SZ / NSPLIT))) * DM + h * DK;
    const __half* Kg = Kp + rb;
    const __half* Vg = Vp + rb;

    float4 a0 = {0,0,0,0}, a1 = {0,0,0,0}, a2 = {0,0,0,0}, a3 = {0,0,0,0};
    float sk = 0.0f;

    const int n = tid >> 3;
    const int qc = (tid & 7) * 8;

    for (int ch = 0; ch < (L_SZ / NSPLIT) / 32; ch++) {
        {
            union { uint4 u; __half2 h[4]; } UK, UV;
            UK.u = *(const uint4*)&Kg[(size_t)(ch * 32 + n) * DM + qc];
            UV.u = *(const uint4*)&Vg[(size_t)(ch * 32 + n) * DM + qc];
#pragma unroll
            for (int j = 0; j < 4; j++) {
                float2 fk = __half22float2(UK.h[j]);
                float2 fv = __half22float2(UV.h[j]);
                Ks[n * 64 + qc + 2 * j]     = fk.x;
                Ks[n * 64 + qc + 2 * j + 1] = fk.y;
                Vs[n * 64 + qc + 2 * j]     = fv.x;
                Vs[n * 64 + qc + 2 * j + 1] = fv.y;
            }
        }
        __syncthreads();
#pragma unroll 4
        for (int nn = 0; nn < 32; nn++) {
            float kd = Ks[nn * 64 + dt];
            sk += kd;
            const float4* vr = (const float4*)&Vs[nn * 64 + mq * 16];
            float4 v0 = vr[0], v1 = vr[1], v2 = vr[2], v3 = vr[3];
            a0.x += kd * v0.x; a0.y += kd * v0.y; a0.z += kd * v0.z; a0.w += kd * v0.w;
            a1.x += kd * v1.x; a1.y += kd * v1.y; a1.z += kd * v1.z; a1.w += kd * v1.w;
            a2.x += kd * v2.x; a2.y += kd * v2.y; a2.z += kd * v2.z; a2.w += kd * v2.w;
            a3.x += kd * v3.x; a3.y += kd * v3.y; a3.z += kd * v3.z; a3.w += kd * v3.w;
        }
        __syncthreads();
    }

    float4* o = (float4*)(g_kv_part + ((size_t)(s * BH + bh)) * (DK * DK) + dt * DK + mq * 16);
    o[0] = a0; o[1] = a1; o[2] = a2; o[3] = a3;
    if (mq == 0) g_ks_part[(s * BH + bh) * DK + dt] = sk;
}

__global__ __launch_bounds__(256)
void kv_combine_kernel()
{
    const int bh = blockIdx.x;
    const int t = threadIdx.x;
#pragma unroll
    for (int j = 0; j < 16; j++) {
        int e = t + j * 256;
        float sum = 0.0f;
#pragma unroll
        for (int s = 0; s < NSPLIT; s++)
            sum += g_kv_part[((size_t)(s * BH + bh)) * (DK * DK) + e];
        g_KV[(size_t)bh * (DK * DK) + e] = sum;
    }
    if (t < DK) {
        float sum = 0.0f;
#pragma unroll
        for (int s = 0; s < NSPLIT; s++)
            sum += g_ks_part[(s * BH + bh) * DK + t];
        g_Ksum[bh * DK + t] = sum;
    }
}

// ---------------- Mid(fp16) = Z * (Q @ KV) ----------------------------------
__global__ __launch_bounds__(256)
void attn_apply_kernel(const __half* __restrict__ Qp, __half* __restrict__ Mid)
{
    const int lc = blockIdx.x;
    const int bh = blockIdx.y;
    const int b = bh >> 4;
    const int h = bh & 15;

    __shared__ float KVs[DK * DK];
    __shared__ float Qs[64 * 68];
    __shared__ float Kss[DK];

    const int tid = threadIdx.x;
    const __half* Qg = Qp + ((size_t)(b * L_SZ + lc * 64)) * DM + h * DK;

#pragma unroll
    for (int j = 0; j < 4; j++) {
        int i = tid + j * 256;
        ((float4*)KVs)[i] = ((const float4*)(g_KV + (size_t)bh * (DK * DK)))[i];
    }
#pragma unroll
    for (int j = 0; j < 2; j++) {
        int i = tid + j * 256;
        int r = i >> 3, qc = (i & 7) * 8;
        union { uint4 u; __half2 h[4]; } U;
        U.u = *(const uint4*)&Qg[(size_t)r * DM + qc];
#pragma unroll
        for (int jj = 0; jj < 4; jj++) {
            float2 f = __half22float2(U.h[jj]);
            Qs[r * 68 + qc + 2 * jj]     = f.x;
            Qs[r * 68 + qc + 2 * jj + 1] = f.y;
        }
    }
    if (tid < DK) Kss[tid] = g_Ksum[bh * DK + tid];
    __syncthreads();

    const int r = tid >> 2;
    const int mq = tid & 3;

    float dot = 0.0f;
#pragma unroll
    for (int d = 0; d < DK; d++) dot += Qs[r * 68 + d] * Kss[d];
    const float z = 1.0f / (dot + EPS_Z);

    float4 a0 = {0,0,0,0}, a1 = {0,0,0,0}, a2 = {0,0,0,0}, a3 = {0,0,0,0};
#pragma unroll 8
    for (int d = 0; d < DK; d++) {
        float qd = Qs[r * 68 + d];
        const float4* kv = (const float4*)&KVs[d * 64 + mq * 16];
        float4 v0 = kv[0], v1 = kv[1], v2 = kv[2], v3 = kv[3];
        a0.x += qd * v0.x; a0.y += qd * v0.y; a0.z += qd * v0.z; a0.w += qd * v0.w;
        a1.x += qd * v1.x; a1.y += qd * v1.y; a1.z += qd * v1.z; a1.w += qd * v1.w;
        a2.x += qd * v2.x; a2.y += qd * v2.y; a2.z += qd * v2.z; a2.w += qd * v2.w;
        a3.x += qd * v3.x; a3.y += qd * v3.y; a3.z += qd * v3.z; a3.w += qd * v3.w;
    }

    __half* Og = Mid + ((size_t)(b * L_SZ + lc * 64 + r)) * DM + h * DK + mq * 16;
    union { uint4 u; __half2 h[4]; } O0, O1;
    O0.h[0] = __floats2half2_rn(a0.x * z, a0.y * z);
    O0.h[1] = __floats2half2_rn(a0.z * z, a0.w * z);
    O0.h[2] = __floats2half2_rn(a1.x * z, a1.y * z);
    O0.h[3] = __floats2half2_rn(a1.z * z, a1.w * z);
    O1.h[0] = __floats2half2_rn(a2.x * z, a2.y * z);
    O1.h[1] = __floats2half2_rn(a2.z * z, a2.w * z);
    O1.h[2] = __floats2half2_rn(a3.x * z, a3.y * z);
    O1.h[3] = __floats2half2_rn(a3.z * z, a3.w * z);
    *(uint4*)&Og[0] = O0.u;
    *(uint4*)&Og[8] = O1.u;
}

// ---------------- launch -----------------------------------------------------
extern "C" void kernel_launch(void* const* d_in, const int* in_sizes, int n_in,
                              void* d_out, int out_size)
{
    const float* q  = (const float*)d_in[0];
    const float* k  = (const float*)d_in[1];
    const float* v  = (const float*)d_in[2];
    const float* wq = (const float*)d_in[4];
    const float* wk = (const float*)d_in[5];
    const float* wv = (const float*)d_in[6];
    const float* wo = (const float*)d_in[7];
    float* out = (float*)d_out;

    __half *Wh, *Ah, *Qp, *Kp, *Vp, *Mid;
    cudaGetSymbolAddress((void**)&Wh,  g_Wh);
    cudaGetSymbolAddress((void**)&Ah,  g_Ah);
    cudaGetSymbolAddress((void**)&Qp,  g_Qp);
    cudaGetSymbolAddress((void**)&Kp,  g_Kp);
    cudaGetSymbolAddress((void**)&Vp,  g_Vp);
    cudaGetSymbolAddress((void**)&Mid, g_Mid);

    cudaFuncSetAttribute(gemm_qkv, cudaFuncAttributeMaxDynamicSharedMemorySize, GSMEM);
    cudaFuncSetAttribute(gemm_out, cudaFuncAttributeMaxDynamicSharedMemorySize, GSMEM);

    cvt_all<<<4 * WBLK + 3 * ABLK, 256>>>(q, k, v, wq, wk, wv, wo);

    dim3 gq(DM / GBN, ROWS / GBM, 3);      // (8, 64, 3) = 1536 blocks
    gemm_qkv<<<gq, 256, GSMEM>>>(Ah, Wh, Qp, Kp, Vp);

    kv_partial_kernel<<<dim3(NSPLIT, BH), 256>>>(Kp, Vp);
    kv_combine_kernel<<<BH, 256>>>();
    attn_apply_kernel<<<dim3(L_SZ / 64, BH), 256>>>(Qp, Mid);

    dim3 gf(DM / GBN, ROWS / GBM);         // (8, 64) = 512 blocks
    gemm_out<<<gf, 256, GSMEM>>>(Mid, Wh + 3 * (size_t)DM * DM, out);
}

// round 7
// speedup vs baseline: 1.0952x; 1.0188x over previous
#include <cuda_runtime.h>
#include <cuda_fp16.h>
#include <cstdint>

#define B_SZ 4
#define L_SZ 2048
#define DM   1024
#define H_N  16
#define DK   64
#define BH   64
#define ROWS 8192
#define EPS_Z 1e-8f
#define NSPLIT 8

// ---------------- scratch ----------------------------------------------------
__device__ __half g_Wh[4][DM * DM];
__device__ __half g_Ah[3][ROWS * DM];
__device__ __half g_Qp[ROWS * DM];
__device__ __half g_Kp[ROWS * DM];
__device__ __half g_Vp[ROWS * DM];
__device__ __half g_Mid[ROWS * DM];
__device__ float  g_kv_part[NSPLIT * BH * DK * DK];
__device__ float  g_ks_part[NSPLIT * BH * DK];
__device__ float  g_KV[BH * DK * DK];
__device__ float  g_Ksum[BH * DK];

// ---------------- helpers ----------------------------------------------------
__device__ __forceinline__ float feature_map(float x) {
    return x > 0.0f ? x + 1.0f : expf(x);
}
__device__ __forceinline__ uint32_t su32(const void* p) {
    uint32_t a;
    asm("{ .reg .u64 t; cvta.to.shared.u64 t, %1; cvt.u32.u64 %0, t; }" : "=r"(a) : "l"(p));
    return a;
}
#define CP16(s, g) asm volatile("cp.async.cg.shared.global [%0], [%1], 16;" :: "r"(s), "l"(g))
#define CP_COMMIT() asm volatile("cp.async.commit_group;")
#define SWZ(o) ((o) ^ (((o) >> 3) & 0x70))

__device__ __forceinline__ void ldm_x4(uint32_t* r, uint32_t addr) {
    asm volatile("ldmatrix.sync.aligned.m8n8.x4.shared.b16 {%0,%1,%2,%3}, [%4];"
                 : "=r"(r[0]), "=r"(r[1]), "=r"(r[2]), "=r"(r[3]) : "r"(addr));
}
__device__ __forceinline__ void mma_f16(float* d, const uint32_t* a, const uint32_t* b) {
    asm volatile(
        "mma.sync.aligned.m16n8k16.row.col.f32.f16.f16.f32 "
        "{%0,%1,%2,%3},{%4,%5,%6,%7},{%8,%9},{%0,%1,%2,%3};\n"
        : "+f"(d[0]), "+f"(d[1]), "+f"(d[2]), "+f"(d[3])
        : "r"(a[0]), "r"(a[1]), "r"(a[2]), "r"(a[3]),
          "r"(b[0]), "r"(b[1]));
}

// ---------------- fp16 GEMM core (R4 shape): BM=128 BN=256 BK=64 -------------
// 256 threads (8 warps 2x4), warp tile 64x64, f32 accum, 3-stage cp.async.
#define GBM 128
#define GBN 256
#define ABYTES (GBM * 128)        // 16384
#define BBYTES (GBN * 128)        // 32768
#define STAGEB (ABYTES + BBYTES)  // 49152
#define NSTAGE 3
#define GSMEM  (NSTAGE * STAGEB)  // 147456

template <int OUTK>
__device__ __forceinline__
void gemm_core(const __half* __restrict__ A, const __half* __restrict__ W,
               void* __restrict__ Cv, int act, int bm0, int bn0, char* sm)
{
    const int tid = threadIdx.x;
    const int wid = tid >> 5;
    const int lane = tid & 31;
    const int wm = wid >> 2;      // 0..1
    const int wn = wid & 3;       // 0..3
    const int gid = lane >> 2;    // 0..7
    const int tig = lane & 3;     // 0..3

    const __half* Ag = A + (size_t)bm0 * DM;
    const __half* Wg = W + (size_t)bn0 * DM;
    const uint32_t sbase = su32(sm);

    float acc[4][8][4];
#pragma unroll
    for (int mi = 0; mi < 4; mi++)
#pragma unroll
        for (int ni = 0; ni < 8; ni++)
#pragma unroll
            for (int c = 0; c < 4; c++) acc[mi][ni][c] = 0.0f;

    auto load_tile = [&](int stg, int k0) {
        const uint32_t ab = sbase + stg * STAGEB;
        const uint32_t bb = ab + ABYTES;
#pragma unroll
        for (int j = 0; j < 4; j++) {          // A: 1024 x 16B
            int i = tid + j * 256;
            int r = i >> 3, q = i & 7;
            CP16(ab + SWZ(r * 128 + q * 16), Ag + (size_t)r * DM + k0 + q * 8);
        }
#pragma unroll
        for (int j = 0; j < 8; j++) {          // B: 2048 x 16B
            int i = tid + j * 256;
            int r = i >> 3, q = i & 7;
            CP16(bb + SWZ(r * 128 + q * 16), Wg + (size_t)r * DM + k0 + q * 8);
        }
        CP_COMMIT();
    };

    const int KT = DM / 64;    // 16
    load_tile(0, 0);
    load_tile(1, 64);

    const int lrow = lane & 15;
    const int lhi  = (lane >> 4) << 4;

    for (int t = 0; t < KT; t++) {
        const int cur = t % NSTAGE;
        if (t + 2 < KT) {
            load_tile((t + 2) % NSTAGE, (t + 2) * 64);
            asm volatile("cp.async.wait_group 2;");
        } else if (t + 1 < KT) {
            asm volatile("cp.async.wait_group 1;");
        } else {
            asm volatile("cp.async.wait_group 0;");
        }
        __syncthreads();

        const uint32_t ab = sbase + cur * STAGEB;
        const uint32_t bb = ab + ABYTES;

#pragma unroll
        for (int ks = 0; ks < 4; ks++) {       // K=16 steps
            const int kboff = ks * 32 + lhi;
            uint32_t af[4][4];
            uint32_t bf[4][4];
#pragma unroll
            for (int mi = 0; mi < 4; mi++)
                ldm_x4(af[mi], ab + SWZ((wm * 64 + mi * 16 + lrow) * 128 + kboff));
#pragma unroll
            for (int p = 0; p < 4; p++)
                ldm_x4(bf[p], bb + SWZ((wn * 64 + p * 16 + lrow) * 128 + kboff));
#pragma unroll
            for (int mi = 0; mi < 4; mi++)
#pragma unroll
                for (int p = 0; p < 4; p++) {
                    uint32_t b0[2] = { bf[p][0], bf[p][2] };
                    uint32_t b1[2] = { bf[p][1], bf[p][3] };
                    mma_f16(acc[mi][2 * p + 0], af[mi], b0);
                    mma_f16(acc[mi][2 * p + 1], af[mi], b1);
                }
        }
        __syncthreads();
    }

    // epilogue
#pragma unroll
    for (int mi = 0; mi < 4; mi++) {
        int r0 = bm0 + wm * 64 + mi * 16 + gid;
#pragma unroll
        for (int ni = 0; ni < 8; ni++) {
            int c0 = bn0 + wn * 64 + ni * 8 + tig * 2;
            float v0 = acc[mi][ni][0];
            float v1 = acc[mi][ni][1];
            float v2 = acc[mi][ni][2];
            float v3 = acc[mi][ni][3];
            if (act) {
                v0 = feature_map(v0); v1 = feature_map(v1);
                v2 = feature_map(v2); v3 = feature_map(v3);
            }
            if (OUTK) {
                __half* C = (__half*)Cv;
                *(__half2*)&C[(size_t)r0 * DM + c0]       = __floats2half2_rn(v0, v1);
                *(__half2*)&C[(size_t)(r0 + 8) * DM + c0] = __floats2half2_rn(v2, v3);
            } else {
                float* C = (float*)Cv;
                *(float2*)&C[(size_t)r0 * DM + c0]       = make_float2(v0, v1);
                *(float2*)&C[(size_t)(r0 + 8) * DM + c0] = make_float2(v2, v3);
            }
        }
    }
}

// merged Q/K/V projection
__global__ __launch_bounds__(256, 1)
void gemm_qkv(const __half* __restrict__ Ah, const __half* __restrict__ Wh,
              __half* __restrict__ Qp, __half* __restrict__ Kp, __half* __restrict__ Vp)
{
    extern __shared__ __align__(16) char sm[];
    const int z = blockIdx.z;
    const __half* A = Ah + (size_t)z * ROWS * DM;
    const __half* W = Wh + (size_t)z * DM * DM;
    __half* C = (z == 0) ? Qp : (z == 1) ? Kp : Vp;
    gemm_core<1>(A, W, (void*)C, z < 2 ? 1 : 0,
                 blockIdx.y * GBM, blockIdx.x * GBN, sm);
}

__global__ __launch_bounds__(256, 1)
void gemm_out(const __half* __restrict__ Mid, const __half* __restrict__ Wo,
              float* __restrict__ out)
{
    extern __shared__ __align__(16) char sm[];
    gemm_core<0>(Mid, Wo, (void*)out, 0, blockIdx.y * GBM, blockIdx.x * GBN, sm);
}

// ---------------- single fused fp32 -> fp16 convert --------------------------
#define WBLK 1024
#define ABLK 8192
__global__ __launch_bounds__(256)
void cvt_all(const float* __restrict__ q, const float* __restrict__ k,
             const float* __restrict__ v,
             const float* __restrict__ w0, const float* __restrict__ w1,
             const float* __restrict__ w2, const float* __restrict__ w3)
{
    const int b = blockIdx.x;
    const float* in;
    __half* out;
    int i;
    if (b < 4 * WBLK) {
        const float* wsrc[4] = { w0, w1, w2, w3 };
        int w = b >> 10;
        in = wsrc[w];
        out = g_Wh[w];
        i = (b & (WBLK - 1)) * 256 + threadIdx.x;
    } else {
        const float* asrc[3] = { q, k, v };
        int r = b - 4 * WBLK;
        int z = r / ABLK;
        in = asrc[z];
        out = g_Ah[z];
        i = (r % ABLK) * 256 + threadIdx.x;
    }
    float4 x = ((const float4*)in)[i];
    ((__half2*)out)[2 * i]     = __floats2half2_rn(x.x, x.y);
    ((__half2*)out)[2 * i + 1] = __floats2half2_rn(x.z, x.w);
}

// ---------------- per-head KV = K^T V (split over L), fp16 in ---------------
__global__ __launch_bounds__(256)
void kv_partial_kernel(const __half* __restrict__ Kp, const __half* __restrict__ Vp)
{
    const int s  = blockIdx.x;
    const int bh = blockIdx.y;
    const int b  = bh >> 4;
    const int h  = bh & 15;
    __shared__ float Ks[32 * 64];
    __shared__ float Vs[32 * 64];

    const int tid = threadIdx.x;
    const int dt = tid >> 2;
    const int mq = tid & 3;

    const size_t rb = ((size_t)(b * L_SZ + s * (L_SZ / NSPLIT))) * DM + h * DK;
    const __half* Kg = Kp + rb;
    const __half* Vg = Vp + rb;

    float4 a0 = {0,0,0,0}, a1 = {0,0,0,0}, a2 = {0,0,0,0}, a3 = {0,0,0,0};
    float sk = 0.0f;

    const int n = tid >> 3;
    const int qc = (tid & 7) * 8;

    for (int ch = 0; ch < (L_SZ / NSPLIT) / 32; ch++) {
        {
            union { uint4 u; __half2 h[4]; } UK, UV;
            UK.u = *(const uint4*)&Kg[(size_t)(ch * 32 + n) * DM + qc];
            UV.u = *(const uint4*)&Vg[(size_t)(ch * 32 + n) * DM + qc];
#pragma unroll
            for (int j = 0; j < 4; j++) {
                float2 fk = __half22float2(UK.h[j]);
                float2 fv = __half22float2(UV.h[j]);
                Ks[n * 64 + qc + 2 * j]     = fk.x;
                Ks[n * 64 + qc + 2 * j + 1] = fk.y;
                Vs[n * 64 + qc + 2 * j]     = fv.x;
                Vs[n * 64 + qc + 2 * j + 1] = fv.y;
            }
        }
        __syncthreads();
#pragma unroll 4
        for (int nn = 0; nn < 32; nn++) {
            float kd = Ks[nn * 64 + dt];
            sk += kd;
            const float4* vr = (const float4*)&Vs[nn * 64 + mq * 16];
            float4 v0 = vr[0], v1 = vr[1], v2 = vr[2], v3 = vr[3];
            a0.x += kd * v0.x; a0.y += kd * v0.y; a0.z += kd * v0.z; a0.w += kd * v0.w;
            a1.x += kd * v1.x; a1.y += kd * v1.y; a1.z += kd * v1.z; a1.w += kd * v1.w;
            a2.x += kd * v2.x; a2.y += kd * v2.y; a2.z += kd * v2.z; a2.w += kd * v2.w;
            a3.x += kd * v3.x; a3.y += kd * v3.y; a3.z += kd * v3.z; a3.w += kd * v3.w;
        }
        __syncthreads();
    }

    float4* o = (float4*)(g_kv_part + ((size_t)(s * BH + bh)) * (DK * DK) + dt * DK + mq * 16);
    o[0] = a0; o[1] = a1; o[2] = a2; o[3] = a3;
    if (mq == 0) g_ks_part[(s * BH + bh) * DK + dt] = sk;
}

// grid (BH, 4): block (bh, quarter) sums 1024 KV elems over NSPLIT partials
__global__ __launch_bounds__(256)
void kv_combine_kernel()
{
    const int bh = blockIdx.x;
    const int qd = blockIdx.y;
    const int t = threadIdx.x;
    const int e4 = qd * 256 + t;                 // float4 index within 4096 elems
    float4 sum = {0, 0, 0, 0};
#pragma unroll
    for (int s = 0; s < NSPLIT; s++) {
        float4 p = ((const float4*)(g_kv_part + ((size_t)(s * BH + bh)) * (DK * DK)))[e4];
        sum.x += p.x; sum.y += p.y; sum.z += p.z; sum.w += p.w;
    }
    ((float4*)(g_KV + (size_t)bh * (DK * DK)))[e4] = sum;
    if (qd == 0 && t < DK) {
        float s2 = 0.0f;
#pragma unroll
        for (int s = 0; s < NSPLIT; s++)
            s2 += g_ks_part[(s * BH + bh) * DK + t];
        g_Ksum[bh * DK + t] = s2;
    }
}

// ---------------- Mid(fp16) = Z * (Q @ KV) ----------------------------------
__global__ __launch_bounds__(256)
void attn_apply_kernel(const __half* __restrict__ Qp, __half* __restrict__ Mid)
{
    const int lc = blockIdx.x;
    const int bh = blockIdx.y;
    const int b = bh >> 4;
    const int h = bh & 15;

    __shared__ float KVs[DK * DK];
    __shared__ float Qs[64 * 68];
    __shared__ float Kss[DK];

    const int tid = threadIdx.x;
    const __half* Qg = Qp + ((size_t)(b * L_SZ + lc * 64)) * DM + h * DK;

#pragma unroll
    for (int j = 0; j < 4; j++) {
        int i = tid + j * 256;
        ((float4*)KVs)[i] = ((const float4*)(g_KV + (size_t)bh * (DK * DK)))[i];
    }
#pragma unroll
    for (int j = 0; j < 2; j++) {
        int i = tid + j * 256;
        int r = i >> 3, qc = (i & 7) * 8;
        union { uint4 u; __half2 h[4]; } U;
        U.u = *(const uint4*)&Qg[(size_t)r * DM + qc];
#pragma unroll
        for (int jj = 0; jj < 4; jj++) {
            float2 f = __half22float2(U.h[jj]);
            Qs[r * 68 + qc + 2 * jj]     = f.x;
            Qs[r * 68 + qc + 2 * jj + 1] = f.y;
        }
    }
    if (tid < DK) Kss[tid] = g_Ksum[bh * DK + tid];
    __syncthreads();

    const int r = tid >> 2;
    const int mq = tid & 3;

    float dot = 0.0f;
#pragma unroll
    for (int d = 0; d < DK; d++) dot += Qs[r * 68 + d] * Kss[d];
    const float z = 1.0f / (dot + EPS_Z);

    float4 a0 = {0,0,0,0}, a1 = {0,0,0,0}, a2 = {0,0,0,0}, a3 = {0,0,0,0};
#pragma unroll 8
    for (int d = 0; d < DK; d++) {
        float qd = Qs[r * 68 + d];
        const float4* kv = (const float4*)&KVs[d * 64 + mq * 16];
        float4 v0 = kv[0], v1 = kv[1], v2 = kv[2], v3 = kv[3];
        a0.x += qd * v0.x; a0.y += qd * v0.y; a0.z += qd * v0.z; a0.w += qd * v0.w;
        a1.x += qd * v1.x; a1.y += qd * v1.y; a1.z += qd * v1.z; a1.w += qd * v1.w;
        a2.x += qd * v2.x; a2.y += qd * v2.y; a2.z += qd * v2.z; a2.w += qd * v2.w;
        a3.x += qd * v3.x; a3.y += qd * v3.y; a3.z += qd * v3.z; a3.w += qd * v3.w;
    }

    __half* Og = Mid + ((size_t)(b * L_SZ + lc * 64 + r)) * DM + h * DK + mq * 16;
    union { uint4 u; __half2 h[4]; } O0, O1;
    O0.h[0] = __floats2half2_rn(a0.x * z, a0.y * z);
    O0.h[1] = __floats2half2_rn(a0.z * z, a0.w * z);
    O0.h[2] = __floats2half2_rn(a1.x * z, a1.y * z);
    O0.h[3] = __floats2half2_rn(a1.z * z, a1.w * z);
    O1.h[0] = __floats2half2_rn(a2.x * z, a2.y * z);
    O1.h[1] = __floats2half2_rn(a2.z * z, a2.w * z);
    O1.h[2] = __floats2half2_rn(a3.x * z, a3.y * z);
    O1.h[3] = __floats2half2_rn(a3.z * z, a3.w * z);
    *(uint4*)&Og[0] = O0.u;
    *(uint4*)&Og[8] = O1.u;
}

// ---------------- launch -----------------------------------------------------
extern "C" void kernel_launch(void* const* d_in, const int* in_sizes, int n_in,
                              void* d_out, int out_size)
{
    const float* q  = (const float*)d_in[0];
    const float* k  = (const float*)d_in[1];
    const float* v  = (const float*)d_in[2];
    const float* wq = (const float*)d_in[4];
    const float* wk = (const float*)d_in[5];
    const float* wv = (const float*)d_in[6];
    const float* wo = (const float*)d_in[7];
    float* out = (float*)d_out;

    __half *Wh, *Ah, *Qp, *Kp, *Vp, *Mid;
    cudaGetSymbolAddress((void**)&Wh,  g_Wh);
    cudaGetSymbolAddress((void**)&Ah,  g_Ah);
    cudaGetSymbolAddress((void**)&Qp,  g_Qp);
    cudaGetSymbolAddress((void**)&Kp,  g_Kp);
    cudaGetSymbolAddress((void**)&Vp,  g_Vp);
    cudaGetSymbolAddress((void**)&Mid, g_Mid);

    cudaFuncSetAttribute(gemm_qkv, cudaFuncAttributeMaxDynamicSharedMemorySize, GSMEM);
    cudaFuncSetAttribute(gemm_out, cudaFuncAttributeMaxDynamicSharedMemorySize, GSMEM);

    cvt_all<<<4 * WBLK + 3 * ABLK, 256>>>(q, k, v, wq, wk, wv, wo);

    dim3 gq(DM / GBN, ROWS / GBM, 3);      // (4, 64, 3) = 768 blocks
    gemm_qkv<<<gq, 256, GSMEM>>>(Ah, Wh, Qp, Kp, Vp);

    kv_partial_kernel<<<dim3(NSPLIT, BH), 256>>>(Kp, Vp);
    kv_combine_kernel<<<dim3(BH, 4), 256>>>();
    attn_apply_kernel<<<dim3(L_SZ / 64, BH), 256>>>(Qp, Mid);

    dim3 gf(DM / GBN, ROWS / GBM);         // (4, 64) = 256 blocks
    gemm_out<<<gf, 256, GSMEM>>>(Mid, Wh + 3 * (size_t)DM * DM, out);
}

// round 8
// speedup vs baseline: 1.0981x; 1.0027x over previous
#include <cuda_runtime.h>
#include <cuda_fp16.h>
#include <cstdint>

#define B_SZ 4
#define L_SZ 2048
#define DM   1024
#define H_N  16
#define DK   64
#define BH   64
#define ROWS 8192
#define EPS_Z 1e-8f
#define NSPLIT 8

// ---------------- scratch ----------------------------------------------------
__device__ __half g_Wh[4][DM * DM];
__device__ __half g_Ah[3][ROWS * DM];
__device__ __half g_Qp[ROWS * DM];
__device__ __half g_Kp[ROWS * DM];
__device__ __half g_Vp[ROWS * DM];
__device__ __half g_Mid[ROWS * DM];
__device__ float  g_kv_part[NSPLIT * BH * DK * DK];
__device__ float  g_ks_part[NSPLIT * BH * DK];
__device__ float  g_KV[BH * DK * DK];
__device__ float  g_Ksum[BH * DK];

// ---------------- helpers ----------------------------------------------------
__device__ __forceinline__ float feature_map(float x) {
    return x > 0.0f ? x + 1.0f : expf(x);
}
__device__ __forceinline__ uint32_t su32(const void* p) {
    uint32_t a;
    asm("{ .reg .u64 t; cvta.to.shared.u64 t, %1; cvt.u32.u64 %0, t; }" : "=r"(a) : "l"(p));
    return a;
}
#define CP16(s, g) asm volatile("cp.async.cg.shared.global [%0], [%1], 16;" :: "r"(s), "l"(g))
#define CP_COMMIT() asm volatile("cp.async.commit_group;")
#define SWZ(o) ((o) ^ (((o) >> 3) & 0x70))

__device__ __forceinline__ void ldm_x4(uint32_t* r, uint32_t addr) {
    asm volatile("ldmatrix.sync.aligned.m8n8.x4.shared.b16 {%0,%1,%2,%3}, [%4];"
                 : "=r"(r[0]), "=r"(r[1]), "=r"(r[2]), "=r"(r[3]) : "r"(addr));
}
__device__ __forceinline__ void mma_f16(float* d, const uint32_t* a, const uint32_t* b) {
    asm volatile(
        "mma.sync.aligned.m16n8k16.row.col.f32.f16.f16.f32 "
        "{%0,%1,%2,%3},{%4,%5,%6,%7},{%8,%9},{%0,%1,%2,%3};\n"
        : "+f"(d[0]), "+f"(d[1]), "+f"(d[2]), "+f"(d[3])
        : "r"(a[0]), "r"(a[1]), "r"(a[2]), "r"(a[3]),
          "r"(b[0]), "r"(b[1]));
}

// ---------------- fp16 GEMM (R4 exact): BM=128 BN=256 BK=64, 2-stage ---------
#define GBM 128
#define GBN 256
#define ABYTES (GBM * 128)        // 16384
#define BBYTES (GBN * 128)        // 32768
#define STAGEB (ABYTES + BBYTES)  // 49152
#define GSMEM  (2 * STAGEB)       // 98304

template <int ACT, int OUTK>
__global__ __launch_bounds__(256, 1)
void gemm_f16(const __half* __restrict__ A, const __half* __restrict__ W,
              void* __restrict__ Cv)
{
    extern __shared__ __align__(16) char sm[];

    const int tid = threadIdx.x;
    const int wid = tid >> 5;
    const int lane = tid & 31;
    const int wm = wid >> 2;      // 0..1
    const int wn = wid & 3;       // 0..3
    const int gid = lane >> 2;    // 0..7
    const int tig = lane & 3;     // 0..3
    const int bm0 = blockIdx.y * GBM;
    const int bn0 = blockIdx.x * GBN;

    const __half* Ag = A + (size_t)bm0 * DM;
    const __half* Wg = W + (size_t)bn0 * DM;
    const uint32_t sbase = su32(sm);

    float acc[4][8][4];
#pragma unroll
    for (int mi = 0; mi < 4; mi++)
#pragma unroll
        for (int ni = 0; ni < 8; ni++)
#pragma unroll
            for (int c = 0; c < 4; c++) acc[mi][ni][c] = 0.0f;

    auto load_tile = [&](int stg, int k0) {
        const uint32_t ab = sbase + stg * STAGEB;
        const uint32_t bb = ab + ABYTES;
#pragma unroll
        for (int j = 0; j < 4; j++) {          // A: 1024 x 16B chunks
            int i = tid + j * 256;
            int r = i >> 3, q = i & 7;
            CP16(ab + SWZ(r * 128 + q * 16), Ag + (size_t)r * DM + k0 + q * 8);
        }
#pragma unroll
        for (int j = 0; j < 8; j++) {          // B: 2048 x 16B chunks
            int i = tid + j * 256;
            int r = i >> 3, q = i & 7;
            CP16(bb + SWZ(r * 128 + q * 16), Wg + (size_t)r * DM + k0 + q * 8);
        }
        CP_COMMIT();
    };

    const int KT = DM / 64;   // 16
    load_tile(0, 0);

    const int lrow = lane & 15;
    const int lhi  = (lane >> 4) << 4;

    for (int t = 0; t < KT; t++) {
        const int cur = t & 1;
        if (t + 1 < KT) {
            load_tile(cur ^ 1, (t + 1) * 64);
            asm volatile("cp.async.wait_group 1;");
        } else {
            asm volatile("cp.async.wait_group 0;");
        }
        __syncthreads();

        const uint32_t ab = sbase + cur * STAGEB;
        const uint32_t bb = ab + ABYTES;

#pragma unroll
        for (int ks = 0; ks < 4; ks++) {       // k-steps of 16 halfs (32B)
            const int kboff = ks * 32 + lhi;
            uint32_t af[4][4];
            uint32_t bf[4][4];
#pragma unroll
            for (int mi = 0; mi < 4; mi++)
                ldm_x4(af[mi], ab + SWZ((wm * 64 + mi * 16 + lrow) * 128 + kboff));
#pragma unroll
            for (int p = 0; p < 4; p++)
                ldm_x4(bf[p], bb + SWZ((wn * 64 + p * 16 + lrow) * 128 + kboff));
#pragma unroll
            for (int mi = 0; mi < 4; mi++)
#pragma unroll
                for (int p = 0; p < 4; p++) {
                    uint32_t b0[2] = { bf[p][0], bf[p][2] };
                    uint32_t b1[2] = { bf[p][1], bf[p][3] };
                    mma_f16(acc[mi][2 * p + 0], af[mi], b0);
                    mma_f16(acc[mi][2 * p + 1], af[mi], b1);
                }
        }
        __syncthreads();
    }

    // epilogue
#pragma unroll
    for (int mi = 0; mi < 4; mi++) {
        int r0 = bm0 + wm * 64 + mi * 16 + gid;
#pragma unroll
        for (int ni = 0; ni < 8; ni++) {
            int c0 = bn0 + wn * 64 + ni * 8 + tig * 2;
            float v0 = acc[mi][ni][0];
            float v1 = acc[mi][ni][1];
            float v2 = acc[mi][ni][2];
            float v3 = acc[mi][ni][3];
            if (ACT) {
                v0 = feature_map(v0); v1 = feature_map(v1);
                v2 = feature_map(v2); v3 = feature_map(v3);
            }
            if (OUTK) {
                __half* C = (__half*)Cv;
                *(__half2*)&C[(size_t)r0 * DM + c0]       = __floats2half2_rn(v0, v1);
                *(__half2*)&C[(size_t)(r0 + 8) * DM + c0] = __floats2half2_rn(v2, v3);
            } else {
                float* C = (float*)Cv;
                *(float2*)&C[(size_t)r0 * DM + c0]       = make_float2(v0, v1);
                *(float2*)&C[(size_t)(r0 + 8) * DM + c0] = make_float2(v2, v3);
            }
        }
    }
}

// ---------------- single fused fp32 -> fp16 convert (4 float4 / thread) ------
// weights: 4 x 262144 float4s = 256 blocks each; inputs: 3 x 2097152 = 2048 each
__global__ __launch_bounds__(256)
void cvt_all(const float* __restrict__ q, const float* __restrict__ k,
             const float* __restrict__ v,
             const float* __restrict__ w0, const float* __restrict__ w1,
             const float* __restrict__ w2, const float* __restrict__ w3)
{
    const int b = blockIdx.x;
    const float* in;
    __half* out;
    int base;
    if (b < 1024) {
        const float* wsrc[4] = { w0, w1, w2, w3 };
        int w = b >> 8;
        in = wsrc[w];
        out = g_Wh[w];
        base = (b & 255) * 1024;
    } else {
        const float* asrc[3] = { q, k, v };
        int r = b - 1024;
        int z = r >> 11;
        in = asrc[z];
        out = g_Ah[z];
        base = (r & 2047) * 1024;
    }
#pragma unroll
    for (int j = 0; j < 4; j++) {
        int i = base + j * 256 + threadIdx.x;
        float4 x = ((const float4*)in)[i];
        ((__half2*)out)[2 * i]     = __floats2half2_rn(x.x, x.y);
        ((__half2*)out)[2 * i + 1] = __floats2half2_rn(x.z, x.w);
    }
}

// ---------------- per-head KV = K^T V (split over L), fp16 in ---------------
__global__ __launch_bounds__(256)
void kv_partial_kernel(const __half* __restrict__ Kp, const __half* __restrict__ Vp)
{
    const int s  = blockIdx.x;
    const int bh = blockIdx.y;
    const int b  = bh >> 4;
    const int h  = bh & 15;
    __shared__ float Ks[32 * 64];
    __shared__ float Vs[32 * 64];

    const int tid = threadIdx.x;
    const int dt = tid >> 2;
    const int mq = tid & 3;

    const size_t rb = ((size_t)(b * L_SZ + s * (L_SZ / NSPLIT))) * DM + h * DK;
    const __half* Kg = Kp + rb;
    const __half* Vg = Vp + rb;

    float4 a0 = {0,0,0,0}, a1 = {0,0,0,0}, a2 = {0,0,0,0}, a3 = {0,0,0,0};
    float sk = 0.0f;

    const int n = tid >> 3;
    const int qc = (tid & 7) * 8;

    for (int ch = 0; ch < (L_SZ / NSPLIT) / 32; ch++) {
        {
            union { uint4 u; __half2 h[4]; } UK, UV;
            UK.u = *(const uint4*)&Kg[(size_t)(ch * 32 + n) * DM + qc];
            UV.u = *(const uint4*)&Vg[(size_t)(ch * 32 + n) * DM + qc];
#pragma unroll
            for (int j = 0; j < 4; j++) {
                float2 fk = __half22float2(UK.h[j]);
                float2 fv = __half22float2(UV.h[j]);
                Ks[n * 64 + qc + 2 * j]     = fk.x;
                Ks[n * 64 + qc + 2 * j + 1] = fk.y;
                Vs[n * 64 + qc + 2 * j]     = fv.x;
                Vs[n * 64 + qc + 2 * j + 1] = fv.y;
            }
        }
        __syncthreads();
#pragma unroll 4
        for (int nn = 0; nn < 32; nn++) {
            float kd = Ks[nn * 64 + dt];
            sk += kd;
            const float4* vr = (const float4*)&Vs[nn * 64 + mq * 16];
            float4 v0 = vr[0], v1 = vr[1], v2 = vr[2], v3 = vr[3];
            a0.x += kd * v0.x; a0.y += kd * v0.y; a0.z += kd * v0.z; a0.w += kd * v0.w;
            a1.x += kd * v1.x; a1.y += kd * v1.y; a1.z += kd * v1.z; a1.w += kd * v1.w;
            a2.x += kd * v2.x; a2.y += kd * v2.y; a2.z += kd * v2.z; a2.w += kd * v2.w;
            a3.x += kd * v3.x; a3.y += kd * v3.y; a3.z += kd * v3.z; a3.w += kd * v3.w;
        }
        __syncthreads();
    }

    float4* o = (float4*)(g_kv_part + ((size_t)(s * BH + bh)) * (DK * DK) + dt * DK + mq * 16);
    o[0] = a0; o[1] = a1; o[2] = a2; o[3] = a3;
    if (mq == 0) g_ks_part[(s * BH + bh) * DK + dt] = sk;
}

// grid (BH, 4): block (bh, quarter) sums 1024 KV elems over NSPLIT partials
__global__ __launch_bounds__(256)
void kv_combine_kernel()
{
    const int bh = blockIdx.x;
    const int qd = blockIdx.y;
    const int t = threadIdx.x;
    const int e4 = qd * 256 + t;
    float4 sum = {0, 0, 0, 0};
#pragma unroll
    for (int s = 0; s < NSPLIT; s++) {
        float4 p = ((const float4*)(g_kv_part + ((size_t)(s * BH + bh)) * (DK * DK)))[e4];
        sum.x += p.x; sum.y += p.y; sum.z += p.z; sum.w += p.w;
    }
    ((float4*)(g_KV + (size_t)bh * (DK * DK)))[e4] = sum;
    if (qd == 0 && t < DK) {
        float s2 = 0.0f;
#pragma unroll
        for (int s = 0; s < NSPLIT; s++)
            s2 += g_ks_part[(s * BH + bh) * DK + t];
        g_Ksum[bh * DK + t] = s2;
    }
}

// ---------------- Mid(fp16) = Z * (Q @ KV) ----------------------------------
__global__ __launch_bounds__(256)
void attn_apply_kernel(const __half* __restrict__ Qp, __half* __restrict__ Mid)
{
    const int lc = blockIdx.x;
    const int bh = blockIdx.y;
    const int b = bh >> 4;
    const int h = bh & 15;

    __shared__ float KVs[DK * DK];
    __shared__ float Qs[64 * 68];
    __shared__ float Kss[DK];

    const int tid = threadIdx.x;
    const __half* Qg = Qp + ((size_t)(b * L_SZ + lc * 64)) * DM + h * DK;

#pragma unroll
    for (int j = 0; j < 4; j++) {
        int i = tid + j * 256;
        ((float4*)KVs)[i] = ((const float4*)(g_KV + (size_t)bh * (DK * DK)))[i];
    }
#pragma unroll
    for (int j = 0; j < 2; j++) {
        int i = tid + j * 256;
        int r = i >> 3, qc = (i & 7) * 8;
        union { uint4 u; __half2 h[4]; } U;
        U.u = *(const uint4*)&Qg[(size_t)r * DM + qc];
#pragma unroll
        for (int jj = 0; jj < 4; jj++) {
            float2 f = __half22float2(U.h[jj]);
            Qs[r * 68 + qc + 2 * jj]     = f.x;
            Qs[r * 68 + qc + 2 * jj + 1] = f.y;
        }
    }
    if (tid < DK) Kss[tid] = g_Ksum[bh * DK + tid];
    __syncthreads();

    const int r = tid >> 2;
    const int mq = tid & 3;

    float dot = 0.0f;
#pragma unroll
    for (int d = 0; d < DK; d++) dot += Qs[r * 68 + d] * Kss[d];
    const float z = 1.0f / (dot + EPS_Z);

    float4 a0 = {0,0,0,0}, a1 = {0,0,0,0}, a2 = {0,0,0,0}, a3 = {0,0,0,0};
#pragma unroll 8
    for (int d = 0; d < DK; d++) {
        float qd = Qs[r * 68 + d];
        const float4* kv = (const float4*)&KVs[d * 64 + mq * 16];
        float4 v0 = kv[0], v1 = kv[1], v2 = kv[2], v3 = kv[3];
        a0.x += qd * v0.x; a0.y += qd * v0.y; a0.z += qd * v0.z; a0.w += qd * v0.w;
        a1.x += qd * v1.x; a1.y += qd * v1.y; a1.z += qd * v1.z; a1.w += qd * v1.w;
        a2.x += qd * v2.x; a2.y += qd * v2.y; a2.z += qd * v2.z; a2.w += qd * v2.w;
        a3.x += qd * v3.x; a3.y += qd * v3.y; a3.z += qd * v3.z; a3.w += qd * v3.w;
    }

    __half* Og = Mid + ((size_t)(b * L_SZ + lc * 64 + r)) * DM + h * DK + mq * 16;
    union { uint4 u; __half2 h[4]; } O0, O1;
    O0.h[0] = __floats2half2_rn(a0.x * z, a0.y * z);
    O0.h[1] = __floats2half2_rn(a0.z * z, a0.w * z);
    O0.h[2] = __floats2half2_rn(a1.x * z, a1.y * z);
    O0.h[3] = __floats2half2_rn(a1.z * z, a1.w * z);
    O1.h[0] = __floats2half2_rn(a2.x * z, a2.y * z);
    O1.h[1] = __floats2half2_rn(a2.z * z, a2.w * z);
    O1.h[2] = __floats2half2_rn(a3.x * z, a3.y * z);
    O1.h[3] = __floats2half2_rn(a3.z * z, a3.w * z);
    *(uint4*)&Og[0] = O0.u;
    *(uint4*)&Og[8] = O1.u;
}

// ---------------- launch -----------------------------------------------------
extern "C" void kernel_launch(void* const* d_in, const int* in_sizes, int n_in,
                              void* d_out, int out_size)
{
    const float* q  = (const float*)d_in[0];
    const float* k  = (const float*)d_in[1];
    const float* v  = (const float*)d_in[2];
    const float* wq = (const float*)d_in[4];
    const float* wk = (const float*)d_in[5];
    const float* wv = (const float*)d_in[6];
    const float* wo = (const float*)d_in[7];
    float* out = (float*)d_out;

    __half *Wh, *Ah, *Qp, *Kp, *Vp, *Mid;
    cudaGetSymbolAddress((void**)&Wh,  g_Wh);
    cudaGetSymbolAddress((void**)&Ah,  g_Ah);
    cudaGetSymbolAddress((void**)&Qp,  g_Qp);
    cudaGetSymbolAddress((void**)&Kp,  g_Kp);
    cudaGetSymbolAddress((void**)&Vp,  g_Vp);
    cudaGetSymbolAddress((void**)&Mid, g_Mid);

    cudaFuncSetAttribute(gemm_f16<1,1>, cudaFuncAttributeMaxDynamicSharedMemorySize, GSMEM);
    cudaFuncSetAttribute(gemm_f16<0,1>, cudaFuncAttributeMaxDynamicSharedMemorySize, GSMEM);
    cudaFuncSetAttribute(gemm_f16<0,0>, cudaFuncAttributeMaxDynamicSharedMemorySize, GSMEM);

    cvt_all<<<1024 + 3 * 2048, 256>>>(q, k, v, wq, wk, wv, wo);

    dim3 ggrid(DM / GBN, ROWS / GBM);       // (4, 64) = 256 blocks
    gemm_f16<1,1><<<ggrid, 256, GSMEM>>>(Ah + 0 * (size_t)ROWS * DM, Wh + 0 * (size_t)DM * DM, Qp);
    gemm_f16<1,1><<<ggrid, 256, GSMEM>>>(Ah + 1 * (size_t)ROWS * DM, Wh + 1 * (size_t)DM * DM, Kp);
    gemm_f16<0,1><<<ggrid, 256, GSMEM>>>(Ah + 2 * (size_t)ROWS * DM, Wh + 2 * (size_t)DM * DM, Vp);

    kv_partial_kernel<<<dim3(NSPLIT, BH), 256>>>(Kp, Vp);
    kv_combine_kernel<<<dim3(BH, 4), 256>>>();
    attn_apply_kernel<<<dim3(L_SZ / 64, BH), 256>>>(Qp, Mid);

    gemm_f16<0,0><<<ggrid, 256, GSMEM>>>(Mid, Wh + 3 * (size_t)DM * DM, out);
}

// round 9
// speedup vs baseline: 2.0620x; 1.8777x over previous
#include <cuda_runtime.h>
#include <cuda_fp16.h>
#include <cstdint>

#define B_SZ 4
#define L_SZ 2048
#define DM   1024
#define H_N  16
#define DK   64
#define BH   64
#define ROWS 8192
#define EPS_Z 1e-8f
#define NSPLIT 8

// ---------------- scratch ----------------------------------------------------
__device__ __half g_Wh[4][DM * DM];
__device__ __half g_Ah[3][ROWS * DM];
__device__ __half g_Qp[ROWS * DM];
__device__ __half g_Kp[ROWS * DM];
__device__ __half g_Vp[ROWS * DM];
__device__ __half g_Mid[ROWS * DM];
__device__ float  g_kv_part[NSPLIT * BH * DK * DK];
__device__ float  g_ks_part[NSPLIT * BH * DK];
__device__ float  g_KV[BH * DK * DK];
__device__ float  g_Ksum[BH * DK];

// ---------------- helpers ----------------------------------------------------
__device__ __forceinline__ float feature_map(float x) {
    return x > 0.0f ? x + 1.0f : expf(x);
}
__device__ __forceinline__ uint32_t su32(const void* p) {
    uint32_t a;
    asm("{ .reg .u64 t; cvta.to.shared.u64 t, %1; cvt.u32.u64 %0, t; }" : "=r"(a) : "l"(p));
    return a;
}
#define CP16(s, g) asm volatile("cp.async.cg.shared.global [%0], [%1], 16;" :: "r"(s), "l"(g))
#define CP_COMMIT() asm volatile("cp.async.commit_group;")
#define SWZ(o) ((o) ^ (((o) >> 3) & 0x70))

__device__ __forceinline__ void ldm_x4(uint32_t* r, uint32_t addr) {
    asm volatile("ldmatrix.sync.aligned.m8n8.x4.shared.b16 {%0,%1,%2,%3}, [%4];"
                 : "=r"(r[0]), "=r"(r[1]), "=r"(r[2]), "=r"(r[3]) : "r"(addr));
}
__device__ __forceinline__ void ldm_x4_t(uint32_t* r, uint32_t addr) {
    asm volatile("ldmatrix.sync.aligned.m8n8.x4.trans.shared.b16 {%0,%1,%2,%3}, [%4];"
                 : "=r"(r[0]), "=r"(r[1]), "=r"(r[2]), "=r"(r[3]) : "r"(addr));
}
__device__ __forceinline__ void mma_f16(float* d, const uint32_t* a, const uint32_t* b) {
    asm volatile(
        "mma.sync.aligned.m16n8k16.row.col.f32.f16.f16.f32 "
        "{%0,%1,%2,%3},{%4,%5,%6,%7},{%8,%9},{%0,%1,%2,%3};\n"
        : "+f"(d[0]), "+f"(d[1]), "+f"(d[2]), "+f"(d[3])
        : "r"(a[0]), "r"(a[1]), "r"(a[2]), "r"(a[3]),
          "r"(b[0]), "r"(b[1]));
}

// ---------------- fp16 GEMM: BM=128 BN=256 BK=64, 512 thr, warp 32x64 --------
#define GBM 128
#define GBN 256
#define ABYTES (GBM * 128)        // 16384
#define BBYTES (GBN * 128)        // 32768
#define STAGEB (ABYTES + BBYTES)  // 49152
#define GSMEM  (2 * STAGEB)       // 98304

template <int ACT, int OUTK>
__global__ __launch_bounds__(512, 1)
void gemm_f16(const __half* __restrict__ A, const __half* __restrict__ W,
              void* __restrict__ Cv)
{
    extern __shared__ __align__(16) char sm[];

    const int tid = threadIdx.x;
    const int wid = tid >> 5;
    const int lane = tid & 31;
    const int wm = wid >> 2;      // 0..3  (M: 4 x 32)
    const int wn = wid & 3;       // 0..3  (N: 4 x 64)
    const int gid = lane >> 2;    // 0..7
    const int tig = lane & 3;     // 0..3
    const int bm0 = blockIdx.y * GBM;
    const int bn0 = blockIdx.x * GBN;

    const __half* Ag = A + (size_t)bm0 * DM;
    const __half* Wg = W + (size_t)bn0 * DM;
    const uint32_t sbase = su32(sm);

    float acc[2][8][4];
#pragma unroll
    for (int mi = 0; mi < 2; mi++)
#pragma unroll
        for (int ni = 0; ni < 8; ni++)
#pragma unroll
            for (int c = 0; c < 4; c++) acc[mi][ni][c] = 0.0f;

    auto load_tile = [&](int stg, int k0) {
        const uint32_t ab = sbase + stg * STAGEB;
        const uint32_t bb = ab + ABYTES;
#pragma unroll
        for (int j = 0; j < 2; j++) {          // A: 1024 x 16B chunks
            int i = tid + j * 512;
            int r = i >> 3, q = i & 7;
            CP16(ab + SWZ(r * 128 + q * 16), Ag + (size_t)r * DM + k0 + q * 8);
        }
#pragma unroll
        for (int j = 0; j < 4; j++) {          // B: 2048 x 16B chunks
            int i = tid + j * 512;
            int r = i >> 3, q = i & 7;
            CP16(bb + SWZ(r * 128 + q * 16), Wg + (size_t)r * DM + k0 + q * 8);
        }
        CP_COMMIT();
    };

    const int KT = DM / 64;   // 16
    load_tile(0, 0);

    const int lrow = lane & 15;
    const int lhi  = (lane >> 4) << 4;

    for (int t = 0; t < KT; t++) {
        const int cur = t & 1;
        if (t + 1 < KT) {
            load_tile(cur ^ 1, (t + 1) * 64);
            asm volatile("cp.async.wait_group 1;");
        } else {
            asm volatile("cp.async.wait_group 0;");
        }
        __syncthreads();

        const uint32_t ab = sbase + cur * STAGEB;
        const uint32_t bb = ab + ABYTES;

#pragma unroll
        for (int ks = 0; ks < 4; ks++) {
            const int kboff = ks * 32 + lhi;
            uint32_t af[2][4];
            uint32_t bf[4][4];
#pragma unroll
            for (int mi = 0; mi < 2; mi++)
                ldm_x4(af[mi], ab + SWZ((wm * 32 + mi * 16 + lrow) * 128 + kboff));
#pragma unroll
            for (int p = 0; p < 4; p++)
                ldm_x4(bf[p], bb + SWZ((wn * 64 + p * 16 + lrow) * 128 + kboff));
#pragma unroll
            for (int mi = 0; mi < 2; mi++)
#pragma unroll
                for (int p = 0; p < 4; p++) {
                    uint32_t b0[2] = { bf[p][0], bf[p][2] };
                    uint32_t b1[2] = { bf[p][1], bf[p][3] };
                    mma_f16(acc[mi][2 * p + 0], af[mi], b0);
                    mma_f16(acc[mi][2 * p + 1], af[mi], b1);
                }
        }
        __syncthreads();
    }

    // epilogue
#pragma unroll
    for (int mi = 0; mi < 2; mi++) {
        int r0 = bm0 + wm * 32 + mi * 16 + gid;
#pragma unroll
        for (int ni = 0; ni < 8; ni++) {
            int c0 = bn0 + wn * 64 + ni * 8 + tig * 2;
            float v0 = acc[mi][ni][0];
            float v1 = acc[mi][ni][1];
            float v2 = acc[mi][ni][2];
            float v3 = acc[mi][ni][3];
            if (ACT) {
                v0 = feature_map(v0); v1 = feature_map(v1);
                v2 = feature_map(v2); v3 = feature_map(v3);
            }
            if (OUTK) {
                __half* C = (__half*)Cv;
                *(__half2*)&C[(size_t)r0 * DM + c0]       = __floats2half2_rn(v0, v1);
                *(__half2*)&C[(size_t)(r0 + 8) * DM + c0] = __floats2half2_rn(v2, v3);
            } else {
                float* C = (float*)Cv;
                *(float2*)&C[(size_t)r0 * DM + c0]       = make_float2(v0, v1);
                *(float2*)&C[(size_t)(r0 + 8) * DM + c0] = make_float2(v2, v3);
            }
        }
    }
}

// ---------------- single fused fp32 -> fp16 convert --------------------------
__global__ __launch_bounds__(256)
void cvt_all(const float* __restrict__ q, const float* __restrict__ k,
             const float* __restrict__ v,
             const float* __restrict__ w0, const float* __restrict__ w1,
             const float* __restrict__ w2, const float* __restrict__ w3)
{
    const int b = blockIdx.x;
    const float* in;
    __half* out;
    int base;
    if (b < 1024) {
        const float* wsrc[4] = { w0, w1, w2, w3 };
        int w = b >> 8;
        in = wsrc[w];
        out = g_Wh[w];
        base = (b & 255) * 1024;
    } else {
        const float* asrc[3] = { q, k, v };
        int r = b - 1024;
        int z = r >> 11;
        in = asrc[z];
        out = g_Ah[z];
        base = (r & 2047) * 1024;
    }
#pragma unroll
    for (int j = 0; j < 4; j++) {
        int i = base + j * 256 + threadIdx.x;
        float4 x = ((const float4*)in)[i];
        ((__half2*)out)[2 * i]     = __floats2half2_rn(x.x, x.y);
        ((__half2*)out)[2 * i + 1] = __floats2half2_rn(x.z, x.w);
    }
}

// ---------------- kv_partial via tensor cores --------------------------------
// grid (NSPLIT, BH), 128 threads (4 warps). KV_part[64d][64m] += K^T V over 256 n.
// A = K^T via ldmatrix.trans, B = V^T via ldmatrix.trans, Ksum via ones-mma.
__global__ __launch_bounds__(128)
void kv_partial_kernel(const __half* __restrict__ Kp, const __half* __restrict__ Vp)
{
    __shared__ __align__(16) __half Ks[2][64 * 64];
    __shared__ __align__(16) __half Vs[2][64 * 64];

    const int s  = blockIdx.x;
    const int bh = blockIdx.y;
    const int b  = bh >> 4;
    const int h  = bh & 15;
    const int tid = threadIdx.x;
    const int w = tid >> 5;
    const int lane = tid & 31;
    const int gid = lane >> 2;
    const int tig = lane & 3;

    const size_t rb = ((size_t)(b * L_SZ + s * (L_SZ / NSPLIT))) * DM + h * DK;
    const __half* Kg = Kp + rb;
    const __half* Vg = Vp + rb;

    const uint32_t ksb[2] = { su32(Ks[0]), su32(Ks[1]) };
    const uint32_t vsb[2] = { su32(Vs[0]), su32(Vs[1]) };

    auto load_chunk = [&](int buf, int n0) {
#pragma unroll
        for (int j = 0; j < 4; j++) {         // 512 chunks each matrix
            int i = tid + j * 128;
            int r = i >> 3, q = i & 7;
            CP16(ksb[buf] + SWZ(r * 128 + q * 16), Kg + (size_t)(n0 + r) * DM + q * 8);
            CP16(vsb[buf] + SWZ(r * 128 + q * 16), Vg + (size_t)(n0 + r) * DM + q * 8);
        }
        CP_COMMIT();
    };

    float accv[8][4];
#pragma unroll
    for (int ni = 0; ni < 8; ni++)
#pragma unroll
        for (int c = 0; c < 4; c++) accv[ni][c] = 0.0f;
    float accs[4] = {0, 0, 0, 0};

    // trans-ldmatrix lane addressing
    const int trow = ((lane & 16) >> 1) + (lane & 7);   // source row 0..15
    const int tcol = (lane & 8) << 1;                   // byte col 0 or 16

    load_chunk(0, 0);

    const uint32_t ONES2 = 0x3C003C00u;   // (1.0h, 1.0h)

    for (int ch = 0; ch < 4; ch++) {
        const int cur = ch & 1;
        if (ch < 3) {
            load_chunk(cur ^ 1, (ch + 1) * 64);
            asm volatile("cp.async.wait_group 1;");
        } else {
            asm volatile("cp.async.wait_group 0;");
        }
        __syncthreads();

#pragma unroll
        for (int kk = 0; kk < 4; kk++) {      // 16-n steps within 64
            uint32_t af[4];
            ldm_x4_t(af, ksb[cur] + SWZ((kk * 16 + trow) * 128 + w * 32 + tcol));
            uint32_t bf[4][4];
#pragma unroll
            for (int p = 0; p < 4; p++)
                ldm_x4_t(bf[p], vsb[cur] + SWZ((kk * 16 + trow) * 128 + p * 32 + tcol));
#pragma unroll
            for (int p = 0; p < 4; p++) {
                uint32_t b0[2] = { bf[p][0], bf[p][2] };
                uint32_t b1[2] = { bf[p][1], bf[p][3] };
                mma_f16(accv[2 * p + 0], af, b0);
                mma_f16(accv[2 * p + 1], af, b1);
            }
            uint32_t bo[2] = { ONES2, ONES2 };
            mma_f16(accs, af, bo);
        }
        __syncthreads();
    }

    // write partials: warp w owns d rows w*16 + {gid, gid+8}
    float* outp = g_kv_part + ((size_t)(s * BH + bh)) * (DK * DK);
    const int r0 = w * 16 + gid;
#pragma unroll
    for (int ni = 0; ni < 8; ni++) {
        int c0 = ni * 8 + tig * 2;
        *(float2*)&outp[r0 * DK + c0]       = make_float2(accv[ni][0], accv[ni][1]);
        *(float2*)&outp[(r0 + 8) * DK + c0] = make_float2(accv[ni][2], accv[ni][3]);
    }
    if (tig == 0) {
        g_ks_part[(s * BH + bh) * DK + r0]     = accs[0];
        g_ks_part[(s * BH + bh) * DK + r0 + 8] = accs[2];
    }
}

// grid (BH, 4): sums partials
__global__ __launch_bounds__(256)
void kv_combine_kernel()
{
    const int bh = blockIdx.x;
    const int qd = blockIdx.y;
    const int t = threadIdx.x;
    const int e4 = qd * 256 + t;
    float4 sum = {0, 0, 0, 0};
#pragma unroll
    for (int s = 0; s < NSPLIT; s++) {
        float4 p = ((const float4*)(g_kv_part + ((size_t)(s * BH + bh)) * (DK * DK)))[e4];
        sum.x += p.x; sum.y += p.y; sum.z += p.z; sum.w += p.w;
    }
    ((float4*)(g_KV + (size_t)bh * (DK * DK)))[e4] = sum;
    if (qd == 0 && t < DK) {
        float s2 = 0.0f;
#pragma unroll
        for (int s = 0; s < NSPLIT; s++)
            s2 += g_ks_part[(s * BH + bh) * DK + t];
        g_Ksum[bh * DK + t] = s2;
    }
}

// ---------------- attn_apply via tensor cores --------------------------------
// grid (L/64, BH), 128 threads (4 warps). Mid = z * (Q @ KV), fp16 out.
__global__ __launch_bounds__(128)
void attn_apply_kernel(const __half* __restrict__ Qp, __half* __restrict__ Mid)
{
    __shared__ __align__(16) __half Qs[64 * 64];
    __shared__ __align__(16) __half KVh[64 * 64];
    __shared__ float Kss[DK];
    __shared__ float zp[128];
    __shared__ float zs[64];

    const int lc = blockIdx.x;
    const int bh = blockIdx.y;
    const int b = bh >> 4;
    const int h = bh & 15;
    const int tid = threadIdx.x;
    const int w = tid >> 5;
    const int lane = tid & 31;
    const int gid = lane >> 2;
    const int tig = lane & 3;

    const __half* Qg = Qp + ((size_t)(b * L_SZ + lc * 64)) * DM + h * DK;
    const uint32_t qsb = su32(Qs);
    const uint32_t kvb = su32(KVh);

    // Q tile: 64 rows x 128B, swizzled, via cp.async
#pragma unroll
    for (int j = 0; j < 4; j++) {
        int i = tid + j * 128;
        int r = i >> 3, q = i & 7;
        CP16(qsb + SWZ(r * 128 + q * 16), Qg + (size_t)r * DM + q * 8);
    }
    CP_COMMIT();

    // KV f32 -> fp16 swizzled smem ([d][m] rows of 128B)
    const float* KVg = g_KV + (size_t)bh * (DK * DK);
#pragma unroll
    for (int j = 0; j < 16; j++) {
        int i = tid + j * 128;              // float2 index, 2048 total
        float2 p = ((const float2*)KVg)[i];
        int d = i >> 5, m = (i & 31) * 2;
        *(__half2*)((char*)KVh + SWZ(d * 128 + m * 2)) = __floats2half2_rn(p.x, p.y);
    }
    if (tid < DK) Kss[tid] = g_Ksum[bh * DK + tid];
    asm volatile("cp.async.wait_group 0;");
    __syncthreads();

    // z: two threads per row
    {
        const int r = tid & 63;
        const int hs = (tid >> 6) * 32;
        float p = 0.0f;
#pragma unroll
        for (int d = 0; d < 32; d++) {
            __half qv = *(const __half*)((const char*)Qs + SWZ(r * 128 + (hs + d) * 2));
            p += __half2float(qv) * Kss[hs + d];
        }
        zp[tid] = p;
    }
    __syncthreads();
    if (tid < 64) zs[tid] = 1.0f / (zp[tid] + zp[tid + 64] + EPS_Z);
    __syncthreads();

    // mma: warp w rows w*16..+15; K-dim = d (64), N = m (64)
    float acc[8][4];
#pragma unroll
    for (int ni = 0; ni < 8; ni++)
#pragma unroll
        for (int c = 0; c < 4; c++) acc[ni][c] = 0.0f;

    const int lrow = lane & 15;
    const int lhi  = (lane >> 4) << 4;
    const int trow = ((lane & 16) >> 1) + (lane & 7);
    const int tcol = (lane & 8) << 1;

#pragma unroll
    for (int ks = 0; ks < 4; ks++) {        // d-steps of 16
        uint32_t af[4];
        ldm_x4(af, qsb + SWZ((w * 16 + lrow) * 128 + ks * 32 + lhi));
        uint32_t bf[4][4];
#pragma unroll
        for (int p = 0; p < 4; p++)
            ldm_x4_t(bf[p], kvb + SWZ((ks * 16 + trow) * 128 + p * 32 + tcol));
#pragma unroll
        for (int p = 0; p < 4; p++) {
            uint32_t b0[2] = { bf[p][0], bf[p][2] };
            uint32_t b1[2] = { bf[p][1], bf[p][3] };
            mma_f16(acc[2 * p + 0], af, b0);
            mma_f16(acc[2 * p + 1], af, b1);
        }
    }

    // scale by z and store fp16
    const int r0 = w * 16 + gid;
    const float z0 = zs[r0];
    const float z1 = zs[r0 + 8];
    __half* Og = Mid + ((size_t)(b * L_SZ + lc * 64)) * DM + h * DK;
#pragma unroll
    for (int ni = 0; ni < 8; ni++) {
        int c0 = ni * 8 + tig * 2;
        *(__half2*)&Og[(size_t)r0 * DM + c0] =
            __floats2half2_rn(acc[ni][0] * z0, acc[ni][1] * z0);
        *(__half2*)&Og[(size_t)(r0 + 8) * DM + c0] =
            __floats2half2_rn(acc[ni][2] * z1, acc[ni][3] * z1);
    }
}

// ---------------- launch -----------------------------------------------------
extern "C" void kernel_launch(void* const* d_in, const int* in_sizes, int n_in,
                              void* d_out, int out_size)
{
    const float* q  = (const float*)d_in[0];
    const float* k  = (const float*)d_in[1];
    const float* v  = (const float*)d_in[2];
    const float* wq = (const float*)d_in[4];
    const float* wk = (const float*)d_in[5];
    const float* wv = (const float*)d_in[6];
    const float* wo = (const float*)d_in[7];
    float* out = (float*)d_out;

    __half *Wh, *Ah, *Qp, *Kp, *Vp, *Mid;
    cudaGetSymbolAddress((void**)&Wh,  g_Wh);
    cudaGetSymbolAddress((void**)&Ah,  g_Ah);
    cudaGetSymbolAddress((void**)&Qp,  g_Qp);
    cudaGetSymbolAddress((void**)&Kp,  g_Kp);
    cudaGetSymbolAddress((void**)&Vp,  g_Vp);
    cudaGetSymbolAddress((void**)&Mid, g_Mid);

    cudaFuncSetAttribute(gemm_f16<1,1>, cudaFuncAttributeMaxDynamicSharedMemorySize, GSMEM);
    cudaFuncSetAttribute(gemm_f16<0,1>, cudaFuncAttributeMaxDynamicSharedMemorySize, GSMEM);
    cudaFuncSetAttribute(gemm_f16<0,0>, cudaFuncAttributeMaxDynamicSharedMemorySize, GSMEM);

    cvt_all<<<1024 + 3 * 2048, 256>>>(q, k, v, wq, wk, wv, wo);

    dim3 ggrid(DM / GBN, ROWS / GBM);       // (4, 64) = 256 blocks
    gemm_f16<1,1><<<ggrid, 512, GSMEM>>>(Ah + 0 * (size_t)ROWS * DM, Wh + 0 * (size_t)DM * DM, Qp);
    gemm_f16<1,1><<<ggrid, 512, GSMEM>>>(Ah + 1 * (size_t)ROWS * DM, Wh + 1 * (size_t)DM * DM, Kp);
    gemm_f16<0,1><<<ggrid, 512, GSMEM>>>(Ah + 2 * (size_t)ROWS * DM, Wh + 2 * (size_t)DM * DM, Vp);

    kv_partial_kernel<<<dim3(NSPLIT, BH), 128>>>(Kp, Vp);
    kv_combine_kernel<<<dim3(BH, 4), 256>>>();
    attn_apply_kernel<<<dim3(L_SZ / 64, BH), 128>>>(Qp, Mid);

    gemm_f16<0,0><<<ggrid, 512, GSMEM>>>(Mid, Wh + 3 * (size_t)DM * DM, out);
}

// round 10
// speedup vs baseline: 2.1048x; 1.0208x over previous
#include <cuda_runtime.h>
#include <cuda_fp16.h>
#include <cstdint>

#define B_SZ 4
#define L_SZ 2048
#define DM   1024
#define H_N  16
#define DK   64
#define BH   64
#define ROWS 8192
#define EPS_Z 1e-8f
#define NSPLIT 8

// ---------------- scratch ----------------------------------------------------
__device__ __half g_Wh[4][DM * DM];
__device__ __half g_Ah[3][ROWS * DM];
__device__ __half g_Qp[ROWS * DM];
__device__ __half g_Kp[ROWS * DM];
__device__ __half g_Vp[ROWS * DM];
__device__ __half g_Mid[ROWS * DM];
__device__ float  g_kv_part[NSPLIT * BH * DK * DK];
__device__ float  g_ks_part[NSPLIT * BH * DK];
__device__ float  g_KV[BH * DK * DK];
__device__ float  g_Ksum[BH * DK];

// ---------------- helpers ----------------------------------------------------
__device__ __forceinline__ float feature_map(float x) {
    return x > 0.0f ? x + 1.0f : expf(x);
}
__device__ __forceinline__ uint32_t su32(const void* p) {
    uint32_t a;
    asm("{ .reg .u64 t; cvta.to.shared.u64 t, %1; cvt.u32.u64 %0, t; }" : "=r"(a) : "l"(p));
    return a;
}
#define CP16(s, g) asm volatile("cp.async.cg.shared.global [%0], [%1], 16;" :: "r"(s), "l"(g))
#define CP_COMMIT() asm volatile("cp.async.commit_group;")
#define SWZ(o) ((o) ^ (((o) >> 3) & 0x70))

__device__ __forceinline__ void ldm_x4(uint32_t* r, uint32_t addr) {
    asm volatile("ldmatrix.sync.aligned.m8n8.x4.shared.b16 {%0,%1,%2,%3}, [%4];"
                 : "=r"(r[0]), "=r"(r[1]), "=r"(r[2]), "=r"(r[3]) : "r"(addr));
}
__device__ __forceinline__ void ldm_x4_t(uint32_t* r, uint32_t addr) {
    asm volatile("ldmatrix.sync.aligned.m8n8.x4.trans.shared.b16 {%0,%1,%2,%3}, [%4];"
                 : "=r"(r[0]), "=r"(r[1]), "=r"(r[2]), "=r"(r[3]) : "r"(addr));
}
__device__ __forceinline__ void mma_f16(float* d, const uint32_t* a, const uint32_t* b) {
    asm volatile(
        "mma.sync.aligned.m16n8k16.row.col.f32.f16.f16.f32 "
        "{%0,%1,%2,%3},{%4,%5,%6,%7},{%8,%9},{%0,%1,%2,%3};\n"
        : "+f"(d[0]), "+f"(d[1]), "+f"(d[2]), "+f"(d[3])
        : "r"(a[0]), "r"(a[1]), "r"(a[2]), "r"(a[3]),
          "r"(b[0]), "r"(b[1]));
}

// ---------------- fp16 GEMM core (R9 exact): BM=128 BN=256 BK=64 -------------
// 512 threads (16 warps 4x4), warp tile 32x64, f32 accum, 2-stage cp.async.
#define GBM 128
#define GBN 256
#define ABYTES (GBM * 128)        // 16384
#define BBYTES (GBN * 128)        // 32768
#define STAGEB (ABYTES + BBYTES)  // 49152
#define GSMEM  (2 * STAGEB)       // 98304

template <int OUTK>
__device__ __forceinline__
void gemm_core(const __half* __restrict__ A, const __half* __restrict__ W,
               void* __restrict__ Cv, int act, int bm0, int bn0, char* sm)
{
    const int tid = threadIdx.x;
    const int wid = tid >> 5;
    const int lane = tid & 31;
    const int wm = wid >> 2;      // 0..3  (M: 4 x 32)
    const int wn = wid & 3;       // 0..3  (N: 4 x 64)
    const int gid = lane >> 2;    // 0..7
    const int tig = lane & 3;     // 0..3

    const __half* Ag = A + (size_t)bm0 * DM;
    const __half* Wg = W + (size_t)bn0 * DM;
    const uint32_t sbase = su32(sm);

    float acc[2][8][4];
#pragma unroll
    for (int mi = 0; mi < 2; mi++)
#pragma unroll
        for (int ni = 0; ni < 8; ni++)
#pragma unroll
            for (int c = 0; c < 4; c++) acc[mi][ni][c] = 0.0f;

    auto load_tile = [&](int stg, int k0) {
        const uint32_t ab = sbase + stg * STAGEB;
        const uint32_t bb = ab + ABYTES;
#pragma unroll
        for (int j = 0; j < 2; j++) {          // A: 1024 x 16B chunks
            int i = tid + j * 512;
            int r = i >> 3, q = i & 7;
            CP16(ab + SWZ(r * 128 + q * 16), Ag + (size_t)r * DM + k0 + q * 8);
        }
#pragma unroll
        for (int j = 0; j < 4; j++) {          // B: 2048 x 16B chunks
            int i = tid + j * 512;
            int r = i >> 3, q = i & 7;
            CP16(bb + SWZ(r * 128 + q * 16), Wg + (size_t)r * DM + k0 + q * 8);
        }
        CP_COMMIT();
    };

    const int KT = DM / 64;   // 16
    load_tile(0, 0);

    const int lrow = lane & 15;
    const int lhi  = (lane >> 4) << 4;

    for (int t = 0; t < KT; t++) {
        const int cur = t & 1;
        if (t + 1 < KT) {
            load_tile(cur ^ 1, (t + 1) * 64);
            asm volatile("cp.async.wait_group 1;");
        } else {
            asm volatile("cp.async.wait_group 0;");
        }
        __syncthreads();

        const uint32_t ab = sbase + cur * STAGEB;
        const uint32_t bb = ab + ABYTES;

#pragma unroll
        for (int ks = 0; ks < 4; ks++) {
            const int kboff = ks * 32 + lhi;
            uint32_t af[2][4];
            uint32_t bf[4][4];
#pragma unroll
            for (int mi = 0; mi < 2; mi++)
                ldm_x4(af[mi], ab + SWZ((wm * 32 + mi * 16 + lrow) * 128 + kboff));
#pragma unroll
            for (int p = 0; p < 4; p++)
                ldm_x4(bf[p], bb + SWZ((wn * 64 + p * 16 + lrow) * 128 + kboff));
#pragma unroll
            for (int mi = 0; mi < 2; mi++)
#pragma unroll
                for (int p = 0; p < 4; p++) {
                    uint32_t b0[2] = { bf[p][0], bf[p][2] };
                    uint32_t b1[2] = { bf[p][1], bf[p][3] };
                    mma_f16(acc[mi][2 * p + 0], af[mi], b0);
                    mma_f16(acc[mi][2 * p + 1], af[mi], b1);
                }
        }
        __syncthreads();
    }

    // epilogue
#pragma unroll
    for (int mi = 0; mi < 2; mi++) {
        int r0 = bm0 + wm * 32 + mi * 16 + gid;
#pragma unroll
        for (int ni = 0; ni < 8; ni++) {
            int c0 = bn0 + wn * 64 + ni * 8 + tig * 2;
            float v0 = acc[mi][ni][0];
            float v1 = acc[mi][ni][1];
            float v2 = acc[mi][ni][2];
            float v3 = acc[mi][ni][3];
            if (act) {
                v0 = feature_map(v0); v1 = feature_map(v1);
                v2 = feature_map(v2); v3 = feature_map(v3);
            }
            if (OUTK) {
                __half* C = (__half*)Cv;
                *(__half2*)&C[(size_t)r0 * DM + c0]       = __floats2half2_rn(v0, v1);
                *(__half2*)&C[(size_t)(r0 + 8) * DM + c0] = __floats2half2_rn(v2, v3);
            } else {
                float* C = (float*)Cv;
                *(float2*)&C[(size_t)r0 * DM + c0]       = make_float2(v0, v1);
                *(float2*)&C[(size_t)(r0 + 8) * DM + c0] = make_float2(v2, v3);
            }
        }
    }
}

// merged Q/K/V projection: grid.z selects input/weight/output
__global__ __launch_bounds__(512, 1)
void gemm_qkv(const __half* __restrict__ Ah, const __half* __restrict__ Wh,
              __half* __restrict__ Qp, __half* __restrict__ Kp, __half* __restrict__ Vp)
{
    extern __shared__ __align__(16) char sm[];
    const int z = blockIdx.z;
    const __half* A = Ah + (size_t)z * ROWS * DM;
    const __half* W = Wh + (size_t)z * DM * DM;
    __half* C = (z == 0) ? Qp : (z == 1) ? Kp : Vp;
    gemm_core<1>(A, W, (void*)C, z < 2 ? 1 : 0,
                 blockIdx.y * GBM, blockIdx.x * GBN, sm);
}

__global__ __launch_bounds__(512, 1)
void gemm_out(const __half* __restrict__ Mid, const __half* __restrict__ Wo,
              float* __restrict__ out)
{
    extern __shared__ __align__(16) char sm[];
    gemm_core<0>(Mid, Wo, (void*)out, 0, blockIdx.y * GBM, blockIdx.x * GBN, sm);
}

// ---------------- single fused fp32 -> fp16 convert --------------------------
__global__ __launch_bounds__(256)
void cvt_all(const float* __restrict__ q, const float* __restrict__ k,
             const float* __restrict__ v,
             const float* __restrict__ w0, const float* __restrict__ w1,
             const float* __restrict__ w2, const float* __restrict__ w3)
{
    const int b = blockIdx.x;
    const float* in;
    __half* out;
    int base;
    if (b < 1024) {
        const float* wsrc[4] = { w0, w1, w2, w3 };
        int w = b >> 8;
        in = wsrc[w];
        out = g_Wh[w];
        base = (b & 255) * 1024;
    } else {
        const float* asrc[3] = { q, k, v };
        int r = b - 1024;
        int z = r >> 11;
        in = asrc[z];
        out = g_Ah[z];
        base = (r & 2047) * 1024;
    }
#pragma unroll
    for (int j = 0; j < 4; j++) {
        int i = base + j * 256 + threadIdx.x;
        float4 x = ((const float4*)in)[i];
        ((__half2*)out)[2 * i]     = __floats2half2_rn(x.x, x.y);
        ((__half2*)out)[2 * i + 1] = __floats2half2_rn(x.z, x.w);
    }
}

// ---------------- kv_partial via tensor cores --------------------------------
__global__ __launch_bounds__(128)
void kv_partial_kernel(const __half* __restrict__ Kp, const __half* __restrict__ Vp)
{
    __shared__ __align__(16) __half Ks[2][64 * 64];
    __shared__ __align__(16) __half Vs[2][64 * 64];

    const int s  = blockIdx.x;
    const int bh = blockIdx.y;
    const int b  = bh >> 4;
    const int h  = bh & 15;
    const int tid = threadIdx.x;
    const int w = tid >> 5;
    const int lane = tid & 31;
    const int gid = lane >> 2;
    const int tig = lane & 3;

    const size_t rb = ((size_t)(b * L_SZ + s * (L_SZ / NSPLIT))) * DM + h * DK;
    const __half* Kg = Kp + rb;
    const __half* Vg = Vp + rb;

    const uint32_t ksb[2] = { su32(Ks[0]), su32(Ks[1]) };
    const uint32_t vsb[2] = { su32(Vs[0]), su32(Vs[1]) };

    auto load_chunk = [&](int buf, int n0) {
#pragma unroll
        for (int j = 0; j < 4; j++) {
            int i = tid + j * 128;
            int r = i >> 3, q = i & 7;
            CP16(ksb[buf] + SWZ(r * 128 + q * 16), Kg + (size_t)(n0 + r) * DM + q * 8);
            CP16(vsb[buf] + SWZ(r * 128 + q * 16), Vg + (size_t)(n0 + r) * DM + q * 8);
        }
        CP_COMMIT();
    };

    float accv[8][4];
#pragma unroll
    for (int ni = 0; ni < 8; ni++)
#pragma unroll
        for (int c = 0; c < 4; c++) accv[ni][c] = 0.0f;
    float accs[4] = {0, 0, 0, 0};

    const int trow = ((lane & 16) >> 1) + (lane & 7);
    const int tcol = (lane & 8) << 1;

    load_chunk(0, 0);

    const uint32_t ONES2 = 0x3C003C00u;

    for (int ch = 0; ch < 4; ch++) {
        const int cur = ch & 1;
        if (ch < 3) {
            load_chunk(cur ^ 1, (ch + 1) * 64);
            asm volatile("cp.async.wait_group 1;");
        } else {
            asm volatile("cp.async.wait_group 0;");
        }
        __syncthreads();

#pragma unroll
        for (int kk = 0; kk < 4; kk++) {
            uint32_t af[4];
            ldm_x4_t(af, ksb[cur] + SWZ((kk * 16 + trow) * 128 + w * 32 + tcol));
            uint32_t bf[4][4];
#pragma unroll
            for (int p = 0; p < 4; p++)
                ldm_x4_t(bf[p], vsb[cur] + SWZ((kk * 16 + trow) * 128 + p * 32 + tcol));
#pragma unroll
            for (int p = 0; p < 4; p++) {
                uint32_t b0[2] = { bf[p][0], bf[p][2] };
                uint32_t b1[2] = { bf[p][1], bf[p][3] };
                mma_f16(accv[2 * p + 0], af, b0);
                mma_f16(accv[2 * p + 1], af, b1);
            }
            uint32_t bo[2] = { ONES2, ONES2 };
            mma_f16(accs, af, bo);
        }
        __syncthreads();
    }

    float* outp = g_kv_part + ((size_t)(s * BH + bh)) * (DK * DK);
    const int r0 = w * 16 + gid;
#pragma unroll
    for (int ni = 0; ni < 8; ni++) {
        int c0 = ni * 8 + tig * 2;
        *(float2*)&outp[r0 * DK + c0]       = make_float2(accv[ni][0], accv[ni][1]);
        *(float2*)&outp[(r0 + 8) * DK + c0] = make_float2(accv[ni][2], accv[ni][3]);
    }
    if (tig == 0) {
        g_ks_part[(s * BH + bh) * DK + r0]     = accs[0];
        g_ks_part[(s * BH + bh) * DK + r0 + 8] = accs[2];
    }
}

// grid (BH, 4): sums partials
__global__ __launch_bounds__(256)
void kv_combine_kernel()
{
    const int bh = blockIdx.x;
    const int qd = blockIdx.y;
    const int t = threadIdx.x;
    const int e4 = qd * 256 + t;
    float4 sum = {0, 0, 0, 0};
#pragma unroll
    for (int s = 0; s < NSPLIT; s++) {
        float4 p = ((const float4*)(g_kv_part + ((size_t)(s * BH + bh)) * (DK * DK)))[e4];
        sum.x += p.x; sum.y += p.y; sum.z += p.z; sum.w += p.w;
    }
    ((float4*)(g_KV + (size_t)bh * (DK * DK)))[e4] = sum;
    if (qd == 0 && t < DK) {
        float s2 = 0.0f;
#pragma unroll
        for (int s = 0; s < NSPLIT; s++)
            s2 += g_ks_part[(s * BH + bh) * DK + t];
        g_Ksum[bh * DK + t] = s2;
    }
}

// ---------------- attn_apply via tensor cores --------------------------------
__global__ __launch_bounds__(128)
void attn_apply_kernel(const __half* __restrict__ Qp, __half* __restrict__ Mid)
{
    __shared__ __align__(16) __half Qs[64 * 64];
    __shared__ __align__(16) __half KVh[64 * 64];
    __shared__ float Kss[DK];
    __shared__ float zp[128];
    __shared__ float zs[64];

    const int lc = blockIdx.x;
    const int bh = blockIdx.y;
    const int b = bh >> 4;
    const int h = bh & 15;
    const int tid = threadIdx.x;
    const int w = tid >> 5;
    const int lane = tid & 31;
    const int gid = lane >> 2;
    const int tig = lane & 3;

    const __half* Qg = Qp + ((size_t)(b * L_SZ + lc * 64)) * DM + h * DK;
    const uint32_t qsb = su32(Qs);
    const uint32_t kvb = su32(KVh);

#pragma unroll
    for (int j = 0; j < 4; j++) {
        int i = tid + j * 128;
        int r = i >> 3, q = i & 7;
        CP16(qsb + SWZ(r * 128 + q * 16), Qg + (size_t)r * DM + q * 8);
    }
    CP_COMMIT();

    const float* KVg = g_KV + (size_t)bh * (DK * DK);
#pragma unroll
    for (int j = 0; j < 16; j++) {
        int i = tid + j * 128;
        float2 p = ((const float2*)KVg)[i];
        int d = i >> 5, m = (i & 31) * 2;
        *(__half2*)((char*)KVh + SWZ(d * 128 + m * 2)) = __floats2half2_rn(p.x, p.y);
    }
    if (tid < DK) Kss[tid] = g_Ksum[bh * DK + tid];
    asm volatile("cp.async.wait_group 0;");
    __syncthreads();

    {
        const int r = tid & 63;
        const int hs = (tid >> 6) * 32;
        float p = 0.0f;
#pragma unroll
        for (int d = 0; d < 32; d++) {
            __half qv = *(const __half*)((const char*)Qs + SWZ(r * 128 + (hs + d) * 2));
            p += __half2float(qv) * Kss[hs + d];
        }
        zp[tid] = p;
    }
    __syncthreads();
    if (tid < 64) zs[tid] = 1.0f / (zp[tid] + zp[tid + 64] + EPS_Z);
    __syncthreads();

    float acc[8][4];
#pragma unroll
    for (int ni = 0; ni < 8; ni++)
#pragma unroll
        for (int c = 0; c < 4; c++) acc[ni][c] = 0.0f;

    const int lrow = lane & 15;
    const int lhi  = (lane >> 4) << 4;
    const int trow = ((lane & 16) >> 1) + (lane & 7);
    const int tcol = (lane & 8) << 1;

#pragma unroll
    for (int ks = 0; ks < 4; ks++) {
        uint32_t af[4];
        ldm_x4(af, qsb + SWZ((w * 16 + lrow) * 128 + ks * 32 + lhi));
        uint32_t bf[4][4];
#pragma unroll
        for (int p = 0; p < 4; p++)
            ldm_x4_t(bf[p], kvb + SWZ((ks * 16 + trow) * 128 + p * 32 + tcol));
#pragma unroll
        for (int p = 0; p < 4; p++) {
            uint32_t b0[2] = { bf[p][0], bf[p][2] };
            uint32_t b1[2] = { bf[p][1], bf[p][3] };
            mma_f16(acc[2 * p + 0], af, b0);
            mma_f16(acc[2 * p + 1], af, b1);
        }
    }

    const int r0 = w * 16 + gid;
    const float z0 = zs[r0];
    const float z1 = zs[r0 + 8];
    __half* Og = Mid + ((size_t)(b * L_SZ + lc * 64)) * DM + h * DK;
#pragma unroll
    for (int ni = 0; ni < 8; ni++) {
        int c0 = ni * 8 + tig * 2;
        *(__half2*)&Og[(size_t)r0 * DM + c0] =
            __floats2half2_rn(acc[ni][0] * z0, acc[ni][1] * z0);
        *(__half2*)&Og[(size_t)(r0 + 8) * DM + c0] =
            __floats2half2_rn(acc[ni][2] * z1, acc[ni][3] * z1);
    }
}

// ---------------- launch -----------------------------------------------------
extern "C" void kernel_launch(void* const* d_in, const int* in_sizes, int n_in,
                              void* d_out, int out_size)
{
    const float* q  = (const float*)d_in[0];
    const float* k  = (const float*)d_in[1];
    const float* v  = (const float*)d_in[2];
    const float* wq = (const float*)d_in[4];
    const float* wk = (const float*)d_in[5];
    const float* wv = (const float*)d_in[6];
    const float* wo = (const float*)d_in[7];
    float* out = (float*)d_out;

    __half *Wh, *Ah, *Qp, *Kp, *Vp, *Mid;
    cudaGetSymbolAddress((void**)&Wh,  g_Wh);
    cudaGetSymbolAddress((void**)&Ah,  g_Ah);
    cudaGetSymbolAddress((void**)&Qp,  g_Qp);
    cudaGetSymbolAddress((void**)&Kp,  g_Kp);
    cudaGetSymbolAddress((void**)&Vp,  g_Vp);
    cudaGetSymbolAddress((void**)&Mid, g_Mid);

    cudaFuncSetAttribute(gemm_qkv, cudaFuncAttributeMaxDynamicSharedMemorySize, GSMEM);
    cudaFuncSetAttribute(gemm_out, cudaFuncAttributeMaxDynamicSharedMemorySize, GSMEM);

    cvt_all<<<1024 + 3 * 2048, 256>>>(q, k, v, wq, wk, wv, wo);

    dim3 gq(DM / GBN, ROWS / GBM, 3);       // (4, 64, 3) = 768 blocks
    gemm_qkv<<<gq, 512, GSMEM>>>(Ah, Wh, Qp, Kp, Vp);

    kv_partial_kernel<<<dim3(NSPLIT, BH), 128>>>(Kp, Vp);
    kv_combine_kernel<<<dim3(BH, 4), 256>>>();
    attn_apply_kernel<<<dim3(L_SZ / 64, BH), 128>>>(Qp, Mid);

    dim3 gf(DM / GBN, ROWS / GBM);          // (4, 64) = 256 blocks
    gemm_out<<<gf, 512, GSMEM>>>(Mid, Wh + 3 * (size_t)DM * DM, out);
}

// round 11
// speedup vs baseline: 2.3478x; 1.1154x over previous
#include <cuda_runtime.h>
#include <cuda_fp16.h>
#include <cstdint>

#define B_SZ 4
#define L_SZ 2048
#define DM   1024
#define H_N  16
#define DK   64
#define BH   64
#define ROWS 8192
#define EPS_Z 1e-8f
#define NSPLIT 8

// ---------------- scratch ----------------------------------------------------
__device__ __half g_Wh[4][DM * DM];
__device__ __half g_Ah[3][ROWS * DM];
__device__ __half g_Qp[ROWS * DM];
__device__ __half g_Kp[ROWS * DM];
__device__ __half g_Vp[ROWS * DM];
__device__ __half g_Mid[ROWS * DM];
__device__ float  g_kv_part[NSPLIT * BH * DK * DK];
__device__ float  g_ks_part[NSPLIT * BH * DK];
__device__ float  g_KV[BH * DK * DK];
__device__ float  g_Ksum[BH * DK];

// ---------------- helpers ----------------------------------------------------
__device__ __forceinline__ float feature_map(float x) {
    return x > 0.0f ? x + 1.0f : expf(x);
}
__device__ __forceinline__ uint32_t su32(const void* p) {
    uint32_t a;
    asm("{ .reg .u64 t; cvta.to.shared.u64 t, %1; cvt.u32.u64 %0, t; }" : "=r"(a) : "l"(p));
    return a;
}
#define CP16(s, g) asm volatile("cp.async.cg.shared.global [%0], [%1], 16;" :: "r"(s), "l"(g))
#define CP_COMMIT() asm volatile("cp.async.commit_group;")
#define SWZ(o) ((o) ^ (((o) >> 3) & 0x70))

__device__ __forceinline__ void ldm_x4(uint32_t* r, uint32_t addr) {
    asm volatile("ldmatrix.sync.aligned.m8n8.x4.shared.b16 {%0,%1,%2,%3}, [%4];"
                 : "=r"(r[0]), "=r"(r[1]), "=r"(r[2]), "=r"(r[3]) : "r"(addr));
}
__device__ __forceinline__ void ldm_x4_t(uint32_t* r, uint32_t addr) {
    asm volatile("ldmatrix.sync.aligned.m8n8.x4.trans.shared.b16 {%0,%1,%2,%3}, [%4];"
                 : "=r"(r[0]), "=r"(r[1]), "=r"(r[2]), "=r"(r[3]) : "r"(addr));
}
__device__ __forceinline__ void mma_f16(float* d, const uint32_t* a, const uint32_t* b) {
    asm volatile(
        "mma.sync.aligned.m16n8k16.row.col.f32.f16.f16.f32 "
        "{%0,%1,%2,%3},{%4,%5,%6,%7},{%8,%9},{%0,%1,%2,%3};\n"
        : "+f"(d[0]), "+f"(d[1]), "+f"(d[2]), "+f"(d[3])
        : "r"(a[0]), "r"(a[1]), "r"(a[2]), "r"(a[3]),
          "r"(b[0]), "r"(b[1]));
}

// ---------------- fp16 GEMM core: BM=128 BN=128 BK=64, 256 thr, 2 CTA/SM -----
// 8 warps (4x2), warp tile 32x64, f32 accum, 2-stage cp.async, 64KB smem.
#define GBM 128
#define GBN 128
#define ABYTES (GBM * 128)        // 16384
#define BBYTES (GBN * 128)        // 16384
#define STAGEB (ABYTES + BBYTES)  // 32768
#define GSMEM  (2 * STAGEB)       // 65536

template <int OUTK>
__device__ __forceinline__
void gemm_core(const __half* __restrict__ A, const __half* __restrict__ W,
               void* __restrict__ Cv, int act, int bm0, int bn0, char* sm)
{
    const int tid = threadIdx.x;
    const int wid = tid >> 5;
    const int lane = tid & 31;
    const int wm = wid >> 1;      // 0..3  (M: 4 x 32)
    const int wn = wid & 1;       // 0..1  (N: 2 x 64)
    const int gid = lane >> 2;    // 0..7
    const int tig = lane & 3;     // 0..3

    const __half* Ag = A + (size_t)bm0 * DM;
    const __half* Wg = W + (size_t)bn0 * DM;
    const uint32_t sbase = su32(sm);

    float acc[2][8][4];
#pragma unroll
    for (int mi = 0; mi < 2; mi++)
#pragma unroll
        for (int ni = 0; ni < 8; ni++)
#pragma unroll
            for (int c = 0; c < 4; c++) acc[mi][ni][c] = 0.0f;

    auto load_tile = [&](int stg, int k0) {
        const uint32_t ab = sbase + stg * STAGEB;
        const uint32_t bb = ab + ABYTES;
#pragma unroll
        for (int j = 0; j < 4; j++) {          // A: 1024 x 16B chunks
            int i = tid + j * 256;
            int r = i >> 3, q = i & 7;
            CP16(ab + SWZ(r * 128 + q * 16), Ag + (size_t)r * DM + k0 + q * 8);
        }
#pragma unroll
        for (int j = 0; j < 4; j++) {          // B: 1024 x 16B chunks
            int i = tid + j * 256;
            int r = i >> 3, q = i & 7;
            CP16(bb + SWZ(r * 128 + q * 16), Wg + (size_t)r * DM + k0 + q * 8);
        }
        CP_COMMIT();
    };

    const int KT = DM / 64;   // 16
    load_tile(0, 0);

    const int lrow = lane & 15;
    const int lhi  = (lane >> 4) << 4;

    for (int t = 0; t < KT; t++) {
        const int cur = t & 1;
        if (t + 1 < KT) {
            load_tile(cur ^ 1, (t + 1) * 64);
            asm volatile("cp.async.wait_group 1;");
        } else {
            asm volatile("cp.async.wait_group 0;");
        }
        __syncthreads();

        const uint32_t ab = sbase + cur * STAGEB;
        const uint32_t bb = ab + ABYTES;

#pragma unroll
        for (int ks = 0; ks < 4; ks++) {
            const int kboff = ks * 32 + lhi;
            uint32_t af[2][4];
            uint32_t bf[4][4];
#pragma unroll
            for (int mi = 0; mi < 2; mi++)
                ldm_x4(af[mi], ab + SWZ((wm * 32 + mi * 16 + lrow) * 128 + kboff));
#pragma unroll
            for (int p = 0; p < 4; p++)
                ldm_x4(bf[p], bb + SWZ((wn * 64 + p * 16 + lrow) * 128 + kboff));
#pragma unroll
            for (int mi = 0; mi < 2; mi++)
#pragma unroll
                for (int p = 0; p < 4; p++) {
                    uint32_t b0[2] = { bf[p][0], bf[p][2] };
                    uint32_t b1[2] = { bf[p][1], bf[p][3] };
                    mma_f16(acc[mi][2 * p + 0], af[mi], b0);
                    mma_f16(acc[mi][2 * p + 1], af[mi], b1);
                }
        }
        __syncthreads();
    }

    // epilogue
#pragma unroll
    for (int mi = 0; mi < 2; mi++) {
        int r0 = bm0 + wm * 32 + mi * 16 + gid;
#pragma unroll
        for (int ni = 0; ni < 8; ni++) {
            int c0 = bn0 + wn * 64 + ni * 8 + tig * 2;
            float v0 = acc[mi][ni][0];
            float v1 = acc[mi][ni][1];
            float v2 = acc[mi][ni][2];
            float v3 = acc[mi][ni][3];
            if (act) {
                v0 = feature_map(v0); v1 = feature_map(v1);
                v2 = feature_map(v2); v3 = feature_map(v3);
            }
            if (OUTK) {
                __half* C = (__half*)Cv;
                *(__half2*)&C[(size_t)r0 * DM + c0]       = __floats2half2_rn(v0, v1);
                *(__half2*)&C[(size_t)(r0 + 8) * DM + c0] = __floats2half2_rn(v2, v3);
            } else {
                float* C = (float*)Cv;
                *(float2*)&C[(size_t)r0 * DM + c0]       = make_float2(v0, v1);
                *(float2*)&C[(size_t)(r0 + 8) * DM + c0] = make_float2(v2, v3);
            }
        }
    }
}

// merged Q/K/V projection: grid.z selects input/weight/output
__global__ __launch_bounds__(256, 2)
void gemm_qkv(const __half* __restrict__ Ah, const __half* __restrict__ Wh,
              __half* __restrict__ Qp, __half* __restrict__ Kp, __half* __restrict__ Vp)
{
    extern __shared__ __align__(16) char sm[];
    const int z = blockIdx.z;
    const __half* A = Ah + (size_t)z * ROWS * DM;
    const __half* W = Wh + (size_t)z * DM * DM;
    __half* C = (z == 0) ? Qp : (z == 1) ? Kp : Vp;
    gemm_core<1>(A, W, (void*)C, z < 2 ? 1 : 0,
                 blockIdx.y * GBM, blockIdx.x * GBN, sm);
}

__global__ __launch_bounds__(256, 2)
void gemm_out(const __half* __restrict__ Mid, const __half* __restrict__ Wo,
              float* __restrict__ out)
{
    extern __shared__ __align__(16) char sm[];
    gemm_core<0>(Mid, Wo, (void*)out, 0, blockIdx.y * GBM, blockIdx.x * GBN, sm);
}

// ---------------- single fused fp32 -> fp16 convert --------------------------
__global__ __launch_bounds__(256)
void cvt_all(const float* __restrict__ q, const float* __restrict__ k,
             const float* __restrict__ v,
             const float* __restrict__ w0, const float* __restrict__ w1,
             const float* __restrict__ w2, const float* __restrict__ w3)
{
    const int b = blockIdx.x;
    const float* in;
    __half* out;
    int base;
    if (b < 1024) {
        const float* wsrc[4] = { w0, w1, w2, w3 };
        int w = b >> 8;
        in = wsrc[w];
        out = g_Wh[w];
        base = (b & 255) * 1024;
    } else {
        const float* asrc[3] = { q, k, v };
        int r = b - 1024;
        int z = r >> 11;
        in = asrc[z];
        out = g_Ah[z];
        base = (r & 2047) * 1024;
    }
#pragma unroll
    for (int j = 0; j < 4; j++) {
        int i = base + j * 256 + threadIdx.x;
        float4 x = ((const float4*)in)[i];
        ((__half2*)out)[2 * i]     = __floats2half2_rn(x.x, x.y);
        ((__half2*)out)[2 * i + 1] = __floats2half2_rn(x.z, x.w);
    }
}

// ---------------- kv_partial via tensor cores --------------------------------
__global__ __launch_bounds__(128)
void kv_partial_kernel(const __half* __restrict__ Kp, const __half* __restrict__ Vp)
{
    __shared__ __align__(16) __half Ks[2][64 * 64];
    __shared__ __align__(16) __half Vs[2][64 * 64];

    const int s  = blockIdx.x;
    const int bh = blockIdx.y;
    const int b  = bh >> 4;
    const int h  = bh & 15;
    const int tid = threadIdx.x;
    const int w = tid >> 5;
    const int lane = tid & 31;
    const int gid = lane >> 2;
    const int tig = lane & 3;

    const size_t rb = ((size_t)(b * L_SZ + s * (L_SZ / NSPLIT))) * DM + h * DK;
    const __half* Kg = Kp + rb;
    const __half* Vg = Vp + rb;

    const uint32_t ksb[2] = { su32(Ks[0]), su32(Ks[1]) };
    const uint32_t vsb[2] = { su32(Vs[0]), su32(Vs[1]) };

    auto load_chunk = [&](int buf, int n0) {
#pragma unroll
        for (int j = 0; j < 4; j++) {
            int i = tid + j * 128;
            int r = i >> 3, q = i & 7;
            CP16(ksb[buf] + SWZ(r * 128 + q * 16), Kg + (size_t)(n0 + r) * DM + q * 8);
            CP16(vsb[buf] + SWZ(r * 128 + q * 16), Vg + (size_t)(n0 + r) * DM + q * 8);
        }
        CP_COMMIT();
    };

    float accv[8][4];
#pragma unroll
    for (int ni = 0; ni < 8; ni++)
#pragma unroll
        for (int c = 0; c < 4; c++) accv[ni][c] = 0.0f;
    float accs[4] = {0, 0, 0, 0};

    const int trow = ((lane & 16) >> 1) + (lane & 7);
    const int tcol = (lane & 8) << 1;

    load_chunk(0, 0);

    const uint32_t ONES2 = 0x3C003C00u;

    for (int ch = 0; ch < 4; ch++) {
        const int cur = ch & 1;
        if (ch < 3) {
            load_chunk(cur ^ 1, (ch + 1) * 64);
            asm volatile("cp.async.wait_group 1;");
        } else {
            asm volatile("cp.async.wait_group 0;");
        }
        __syncthreads();

#pragma unroll
        for (int kk = 0; kk < 4; kk++) {
            uint32_t af[4];
            ldm_x4_t(af, ksb[cur] + SWZ((kk * 16 + trow) * 128 + w * 32 + tcol));
            uint32_t bf[4][4];
#pragma unroll
            for (int p = 0; p < 4; p++)
                ldm_x4_t(bf[p], vsb[cur] + SWZ((kk * 16 + trow) * 128 + p * 32 + tcol));
#pragma unroll
            for (int p = 0; p < 4; p++) {
                uint32_t b0[2] = { bf[p][0], bf[p][2] };
                uint32_t b1[2] = { bf[p][1], bf[p][3] };
                mma_f16(accv[2 * p + 0], af, b0);
                mma_f16(accv[2 * p + 1], af, b1);
            }
            uint32_t bo[2] = { ONES2, ONES2 };
            mma_f16(accs, af, bo);
        }
        __syncthreads();
    }

    float* outp = g_kv_part + ((size_t)(s * BH + bh)) * (DK * DK);
    const int r0 = w * 16 + gid;
#pragma unroll
    for (int ni = 0; ni < 8; ni++) {
        int c0 = ni * 8 + tig * 2;
        *(float2*)&outp[r0 * DK + c0]       = make_float2(accv[ni][0], accv[ni][1]);
        *(float2*)&outp[(r0 + 8) * DK + c0] = make_float2(accv[ni][2], accv[ni][3]);
    }
    if (tig == 0) {
        g_ks_part[(s * BH + bh) * DK + r0]     = accs[0];
        g_ks_part[(s * BH + bh) * DK + r0 + 8] = accs[2];
    }
}

// grid (BH, 4): sums partials
__global__ __launch_bounds__(256)
void kv_combine_kernel()
{
    const int bh = blockIdx.x;
    const int qd = blockIdx.y;
    const int t = threadIdx.x;
    const int e4 = qd * 256 + t;
    float4 sum = {0, 0, 0, 0};
#pragma unroll
    for (int s = 0; s < NSPLIT; s++) {
        float4 p = ((const float4*)(g_kv_part + ((size_t)(s * BH + bh)) * (DK * DK)))[e4];
        sum.x += p.x; sum.y += p.y; sum.z += p.z; sum.w += p.w;
    }
    ((float4*)(g_KV + (size_t)bh * (DK * DK)))[e4] = sum;
    if (qd == 0 && t < DK) {
        float s2 = 0.0f;
#pragma unroll
        for (int s = 0; s < NSPLIT; s++)
            s2 += g_ks_part[(s * BH + bh) * DK + t];
        g_Ksum[bh * DK + t] = s2;
    }
}

// ---------------- attn_apply via tensor cores --------------------------------
__global__ __launch_bounds__(128)
void attn_apply_kernel(const __half* __restrict__ Qp, __half* __restrict__ Mid)
{
    __shared__ __align__(16) __half Qs[64 * 64];
    __shared__ __align__(16) __half KVh[64 * 64];
    __shared__ float Kss[DK];
    __shared__ float zp[128];
    __shared__ float zs[64];

    const int lc = blockIdx.x;
    const int bh = blockIdx.y;
    const int b = bh >> 4;
    const int h = bh & 15;
    const int tid = threadIdx.x;
    const int w = tid >> 5;
    const int lane = tid & 31;
    const int gid = lane >> 2;
    const int tig = lane & 3;

    const __half* Qg = Qp + ((size_t)(b * L_SZ + lc * 64)) * DM + h * DK;
    const uint32_t qsb = su32(Qs);
    const uint32_t kvb = su32(KVh);

#pragma unroll
    for (int j = 0; j < 4; j++) {
        int i = tid + j * 128;
        int r = i >> 3, q = i & 7;
        CP16(qsb + SWZ(r * 128 + q * 16), Qg + (size_t)r * DM + q * 8);
    }
    CP_COMMIT();

    const float* KVg = g_KV + (size_t)bh * (DK * DK);
#pragma unroll
    for (int j = 0; j < 16; j++) {
        int i = tid + j * 128;
        float2 p = ((const float2*)KVg)[i];
        int d = i >> 5, m = (i & 31) * 2;
        *(__half2*)((char*)KVh + SWZ(d * 128 + m * 2)) = __floats2half2_rn(p.x, p.y);
    }
    if (tid < DK) Kss[tid] = g_Ksum[bh * DK + tid];
    asm volatile("cp.async.wait_group 0;");
    __syncthreads();

    {
        const int r = tid & 63;
        const int hs = (tid >> 6) * 32;
        float p = 0.0f;
#pragma unroll
        for (int d = 0; d < 32; d++) {
            __half qv = *(const __half*)((const char*)Qs + SWZ(r * 128 + (hs + d) * 2));
            p += __half2float(qv) * Kss[hs + d];
        }
        zp[tid] = p;
    }
    __syncthreads();
    if (tid < 64) zs[tid] = 1.0f / (zp[tid] + zp[tid + 64] + EPS_Z);
    __syncthreads();

    float acc[8][4];
#pragma unroll
    for (int ni = 0; ni < 8; ni++)
#pragma unroll
        for (int c = 0; c < 4; c++) acc[ni][c] = 0.0f;

    const int lrow = lane & 15;
    const int lhi  = (lane >> 4) << 4;
    const int trow = ((lane & 16) >> 1) + (lane & 7);
    const int tcol = (lane & 8) << 1;

#pragma unroll
    for (int ks = 0; ks < 4; ks++) {
        uint32_t af[4];
        ldm_x4(af, qsb + SWZ((w * 16 + lrow) * 128 + ks * 32 + lhi));
        uint32_t bf[4][4];
#pragma unroll
        for (int p = 0; p < 4; p++)
            ldm_x4_t(bf[p], kvb + SWZ((ks * 16 + trow) * 128 + p * 32 + tcol));
#pragma unroll
        for (int p = 0; p < 4; p++) {
            uint32_t b0[2] = { bf[p][0], bf[p][2] };
            uint32_t b1[2] = { bf[p][1], bf[p][3] };
            mma_f16(acc[2 * p + 0], af, b0);
            mma_f16(acc[2 * p + 1], af, b1);
        }
    }

    const int r0 = w * 16 + gid;
    const float z0 = zs[r0];
    const float z1 = zs[r0 + 8];
    __half* Og = Mid + ((size_t)(b * L_SZ + lc * 64)) * DM + h * DK;
#pragma unroll
    for (int ni = 0; ni < 8; ni++) {
        int c0 = ni * 8 + tig * 2;
        *(__half2*)&Og[(size_t)r0 * DM + c0] =
            __floats2half2_rn(acc[ni][0] * z0, acc[ni][1] * z0);
        *(__half2*)&Og[(size_t)(r0 + 8) * DM + c0] =
            __floats2half2_rn(acc[ni][2] * z1, acc[ni][3] * z1);
    }
}

// ---------------- launch -----------------------------------------------------
extern "C" void kernel_launch(void* const* d_in, const int* in_sizes, int n_in,
                              void* d_out, int out_size)
{
    const float* q  = (const float*)d_in[0];
    const float* k  = (const float*)d_in[1];
    const float* v  = (const float*)d_in[2];
    const float* wq = (const float*)d_in[4];
    const float* wk = (const float*)d_in[5];
    const float* wv = (const float*)d_in[6];
    const float* wo = (const float*)d_in[7];
    float* out = (float*)d_out;

    __half *Wh, *Ah, *Qp, *Kp, *Vp, *Mid;
    cudaGetSymbolAddress((void**)&Wh,  g_Wh);
    cudaGetSymbolAddress((void**)&Ah,  g_Ah);
    cudaGetSymbolAddress((void**)&Qp,  g_Qp);
    cudaGetSymbolAddress((void**)&Kp,  g_Kp);
    cudaGetSymbolAddress((void**)&Vp,  g_Vp);
    cudaGetSymbolAddress((void**)&Mid, g_Mid);

    cudaFuncSetAttribute(gemm_qkv, cudaFuncAttributeMaxDynamicSharedMemorySize, GSMEM);
    cudaFuncSetAttribute(gemm_out, cudaFuncAttributeMaxDynamicSharedMemorySize, GSMEM);

    cvt_all<<<1024 + 3 * 2048, 256>>>(q, k, v, wq, wk, wv, wo);

    dim3 gq(DM / GBN, ROWS / GBM, 3);       // (8, 64, 3) = 1536 blocks
    gemm_qkv<<<gq, 256, GSMEM>>>(Ah, Wh, Qp, Kp, Vp);

    kv_partial_kernel<<<dim3(NSPLIT, BH), 128>>>(Kp, Vp);
    kv_combine_kernel<<<dim3(BH, 4), 256>>>();
    attn_apply_kernel<<<dim3(L_SZ / 64, BH), 128>>>(Qp, Mid);

    dim3 gf(DM / GBN, ROWS / GBM);          // (8, 64) = 512 blocks
    gemm_out<<<gf, 256, GSMEM>>>(Mid, Wh + 3 * (size_t)DM * DM, out);
}